// round 2
// baseline (speedup 1.0000x reference)
#include <cuda_runtime.h>
#include <cstdint>
#include <math.h>

// ---------------- problem constants ----------------
#define NE   16
#define HD   1024
#define ID   512
#define ISD  2048
#define NTOK 8192
#define SLOT_CAP (NTOK*2 + NE*128)   // 18432 (each expert region padded to 128)
#define MTILES   (SLOT_CAP/128)      // 144

// ---------------- scratch (device globals; no cudaMalloc allowed) ----------------
__device__ float g_gubuf[(size_t)SLOT_CAP * 1024]; // expert gate_up output [slot][2I]
__device__ float g_hbuf [(size_t)SLOT_CAP * 512];  // silu(g)*u           [slot][I]
__device__ float g_dres [(size_t)SLOT_CAP * 1024]; // expert down output  [slot][H]
__device__ float g_gbuf [(size_t)NTOK * ISD];      // shared gate (then silu(g)*u in place)
__device__ float g_ubuf [(size_t)NTOK * ISD];      // shared up
__device__ float g_shout[(size_t)NTOK * HD];       // shared down output
__device__ int   g_tok_idx[SLOT_CAP];
__device__ int   g_slot_of[NTOK*2];
__device__ int   g_sel[NTOK*2];
__device__ float g_w[NTOK*2];
__device__ float g_sgate[NTOK];
__device__ int   g_cnt[NE];
__device__ float g_probsum[NE];
__device__ int   g_fill[NE];
__device__ int   g_eoff[NE+1];
__device__ int   g_blk_e[MTILES];
__device__ int   g_total;

// ---------------- K0: init ----------------
__global__ void init_kernel() {
    int i = blockIdx.x * blockDim.x + threadIdx.x;
    if (i < SLOT_CAP) g_tok_idx[i] = -1;
    if (i < NE) { g_cnt[i] = 0; g_probsum[i] = 0.f; g_fill[i] = 0; }
}

// ---------------- K1: router (one warp per token) ----------------
__global__ void router_kernel(const float* __restrict__ x,
                              const float* __restrict__ gw,
                              const float* __restrict__ segw, int N) {
    int warp = (blockIdx.x * blockDim.x + threadIdx.x) >> 5;
    int lane = threadIdx.x & 31;
    __shared__ float s_ps[NE];
    __shared__ int   s_cnt[NE];
    if (threadIdx.x < NE) { s_ps[threadIdx.x] = 0.f; s_cnt[threadIdx.x] = 0; }
    __syncthreads();

    if (warp < N) {
        float acc[17];
        #pragma unroll
        for (int j = 0; j < 17; j++) acc[j] = 0.f;
        const float* xr = x + (size_t)warp * HD;
        for (int k = lane; k < HD; k += 32) {
            float xv = __ldg(xr + k);
            #pragma unroll
            for (int j = 0; j < NE; j++) acc[j] += xv * __ldg(gw + j * HD + k);
            acc[16] += xv * __ldg(segw + k);
        }
        #pragma unroll
        for (int j = 0; j < 17; j++) {
            #pragma unroll
            for (int o = 16; o > 0; o >>= 1)
                acc[j] += __shfl_xor_sync(0xffffffffu, acc[j], o);
        }
        // softmax over 16 logits (every lane redundantly)
        float mx = acc[0];
        #pragma unroll
        for (int j = 1; j < NE; j++) mx = fmaxf(mx, acc[j]);
        float p[NE]; float s = 0.f;
        #pragma unroll
        for (int j = 0; j < NE; j++) { p[j] = expf(acc[j] - mx); s += p[j]; }
        float inv = 1.f / s;
        #pragma unroll
        for (int j = 0; j < NE; j++) p[j] *= inv;
        // top-2, ties -> lowest index first (matches jax top_k)
        int a0 = 0;
        #pragma unroll
        for (int j = 1; j < NE; j++) if (p[j] > p[a0]) a0 = j;
        int a1 = (a0 == 0) ? 1 : 0;
        #pragma unroll
        for (int j = 0; j < NE; j++) if (j != a0 && p[j] > p[a1]) a1 = j;
        float ww = p[a0] + p[a1];
        if (lane == 0) {
            g_sel[warp*2]   = a0;  g_sel[warp*2+1] = a1;
            g_w[warp*2]     = p[a0] / ww;
            g_w[warp*2+1]   = p[a1] / ww;
            g_sgate[warp]   = 1.f / (1.f + expf(-acc[16]));
            atomicAdd(&s_cnt[a0], 1); atomicAdd(&s_cnt[a1], 1);
        }
        if (lane < NE) atomicAdd(&s_ps[lane], p[lane]);
    }
    __syncthreads();
    if (threadIdx.x < NE) {
        atomicAdd(&g_probsum[threadIdx.x], s_ps[threadIdx.x]);
        atomicAdd(&g_cnt[threadIdx.x], s_cnt[threadIdx.x]);
    }
}

// ---------------- K2: 128-padded offsets, block->expert table, aux loss ----------------
__global__ void offsets_kernel(float* __restrict__ out, long aux_index, int N) {
    if (threadIdx.x == 0 && blockIdx.x == 0) {
        int off = 0;
        for (int e = 0; e < NE; e++) {
            g_eoff[e] = off;
            off += ((g_cnt[e] + 127) / 128) * 128;
        }
        g_eoff[NE] = off;
        g_total = off;
        for (int e = 0; e < NE; e++)
            for (int t = g_eoff[e] / 128; t < g_eoff[e+1] / 128; t++)
                g_blk_e[t] = e;
        float aux = 0.f;
        for (int e = 0; e < NE; e++)
            aux += ((float)g_cnt[e] / (float)(N * 2)) * (g_probsum[e] / (float)N);
        out[aux_index] = (float)NE * aux;
    }
}

// ---------------- K3: slot assignment ----------------
__global__ void assign_kernel(int N) {
    int t = blockIdx.x * blockDim.x + threadIdx.x;
    if (t < N) {
        #pragma unroll
        for (int i = 0; i < 2; i++) {
            int e = g_sel[t*2 + i];
            int pos = atomicAdd(&g_fill[e], 1);
            int slot = g_eoff[e] + pos;
            g_tok_idx[slot] = t;
            g_slot_of[t*2 + i] = slot;
        }
    }
}

// ---------------- TF32 tiled GEMM: C[M,N] = A[M,K] * B[N,K]^T ----------------
// A optionally row-gathered via row_map (-1 => zero row).
// B optionally per-m-tile expert-selected via blk_e (+ e*estride).
__device__ __forceinline__ float cvt_tf32(float f) {
    unsigned u;
    asm("cvt.rna.tf32.f32 %0, %1;" : "=r"(u) : "f"(f));
    return __uint_as_float(u);
}

#define SMS 136  // smem stride: 136 mod 32 == 8 -> conflict-free fragment loads

__global__ __launch_bounds__(256, 1)
void gemm_tf32(const float* __restrict__ A, const float* __restrict__ B,
               float* __restrict__ C, int M, int N, int K,
               const int* __restrict__ row_map,
               const int* __restrict__ blk_e, long estride,
               int m_from_dev) {
    if (m_from_dev) M = g_total;
    const int m0 = blockIdx.x * 128;
    if (m0 >= M) return;
    const int n0 = blockIdx.y * 128;
    const float* Bp = blk_e ? (B + (long)blk_e[blockIdx.x] * estride) : B;

    __shared__ float As[2][16][SMS];
    __shared__ float Bs[2][16][SMS];

    const int tid  = threadIdx.x;
    const int lane = tid & 31;
    const int wid  = tid >> 5;
    const int wm0  = (wid & 1) * 64;
    const int wn0  = (wid >> 1) * 32;

    float c[4][4][4];
    #pragma unroll
    for (int mi = 0; mi < 4; mi++)
        #pragma unroll
        for (int ni = 0; ni < 4; ni++)
            #pragma unroll
            for (int q = 0; q < 4; q++) c[mi][ni][q] = 0.f;

    // global-load mapping: 4 lanes per row, rows r and r+64, 16 bytes each
    const int row = tid >> 2;          // 0..63
    const int kc  = (tid & 3) * 4;
    long a_off0, a_off1;
    bool a_ok0 = true, a_ok1 = true;
    if (row_map) {
        int r0 = __ldg(&row_map[m0 + row]);
        int r1 = __ldg(&row_map[m0 + row + 64]);
        a_ok0 = (r0 >= 0); a_ok1 = (r1 >= 0);
        a_off0 = (long)(r0 < 0 ? 0 : r0) * K;
        a_off1 = (long)(r1 < 0 ? 0 : r1) * K;
    } else {
        a_off0 = (long)(m0 + row) * K;
        a_off1 = (long)(m0 + row + 64) * K;
    }
    const long b_off0 = (long)(n0 + row) * K;
    const long b_off1 = (long)(n0 + row + 64) * K;

    const int KT = K >> 4;
    const float4 z4 = make_float4(0.f, 0.f, 0.f, 0.f);
    float4 ra0, ra1, rb0, rb1;

    // prologue: tile 0
    ra0 = a_ok0 ? *(const float4*)(A + a_off0 + kc) : z4;
    ra1 = a_ok1 ? *(const float4*)(A + a_off1 + kc) : z4;
    rb0 = *(const float4*)(Bp + b_off0 + kc);
    rb1 = *(const float4*)(Bp + b_off1 + kc);
    {
        float va[4] = {ra0.x, ra0.y, ra0.z, ra0.w};
        float vb[4] = {ra1.x, ra1.y, ra1.z, ra1.w};
        float vc[4] = {rb0.x, rb0.y, rb0.z, rb0.w};
        float vd[4] = {rb1.x, rb1.y, rb1.z, rb1.w};
        #pragma unroll
        for (int j0 = 0; j0 < 4; j0++) {
            int j = (j0 + (tid & 3)) & 3;   // k-rotation kills STS bank conflicts
            As[0][kc + j][row]      = cvt_tf32(va[j]);
            As[0][kc + j][row + 64] = cvt_tf32(vb[j]);
            Bs[0][kc + j][row]      = cvt_tf32(vc[j]);
            Bs[0][kc + j][row + 64] = cvt_tf32(vd[j]);
        }
    }
    __syncthreads();

    const int tg  = lane & 3;
    const int gid = lane >> 2;

    for (int kt = 0; kt < KT; kt++) {
        const int buf = kt & 1;
        if (kt + 1 < KT) {
            int kb = (kt + 1) * 16 + kc;
            ra0 = a_ok0 ? *(const float4*)(A + a_off0 + kb) : z4;
            ra1 = a_ok1 ? *(const float4*)(A + a_off1 + kb) : z4;
            rb0 = *(const float4*)(Bp + b_off0 + kb);
            rb1 = *(const float4*)(Bp + b_off1 + kb);
        }
        #pragma unroll
        for (int ks = 0; ks < 2; ks++) {
            const int kk = ks * 8;
            unsigned a[4][4], b[4][2];
            #pragma unroll
            for (int mi = 0; mi < 4; mi++) {
                int m = wm0 + mi * 16 + gid;
                a[mi][0] = __float_as_uint(As[buf][kk + tg][m]);
                a[mi][1] = __float_as_uint(As[buf][kk + tg][m + 8]);
                a[mi][2] = __float_as_uint(As[buf][kk + 4 + tg][m]);
                a[mi][3] = __float_as_uint(As[buf][kk + 4 + tg][m + 8]);
            }
            #pragma unroll
            for (int ni = 0; ni < 4; ni++) {
                int n = wn0 + ni * 8 + gid;
                b[ni][0] = __float_as_uint(Bs[buf][kk + tg][n]);
                b[ni][1] = __float_as_uint(Bs[buf][kk + 4 + tg][n]);
            }
            #pragma unroll
            for (int mi = 0; mi < 4; mi++)
                #pragma unroll
                for (int ni = 0; ni < 4; ni++)
                    asm volatile(
                        "mma.sync.aligned.m16n8k8.row.col.f32.tf32.tf32.f32 "
                        "{%0,%1,%2,%3}, {%4,%5,%6,%7}, {%8,%9}, {%0,%1,%2,%3};\n"
                        : "+f"(c[mi][ni][0]), "+f"(c[mi][ni][1]),
                          "+f"(c[mi][ni][2]), "+f"(c[mi][ni][3])
                        : "r"(a[mi][0]), "r"(a[mi][1]), "r"(a[mi][2]), "r"(a[mi][3]),
                          "r"(b[ni][0]), "r"(b[ni][1]));
        }
        if (kt + 1 < KT) {
            const int nb = buf ^ 1;
            float va[4] = {ra0.x, ra0.y, ra0.z, ra0.w};
            float vb[4] = {ra1.x, ra1.y, ra1.z, ra1.w};
            float vc[4] = {rb0.x, rb0.y, rb0.z, rb0.w};
            float vd[4] = {rb1.x, rb1.y, rb1.z, rb1.w};
            #pragma unroll
            for (int j0 = 0; j0 < 4; j0++) {
                int j = (j0 + (tid & 3)) & 3;
                As[nb][kc + j][row]      = cvt_tf32(va[j]);
                As[nb][kc + j][row + 64] = cvt_tf32(vb[j]);
                Bs[nb][kc + j][row]      = cvt_tf32(vc[j]);
                Bs[nb][kc + j][row + 64] = cvt_tf32(vd[j]);
            }
            __syncthreads();
        }
    }

    // epilogue
    const int tg2 = (lane & 3) * 2;
    #pragma unroll
    for (int mi = 0; mi < 4; mi++) {
        #pragma unroll
        for (int ni = 0; ni < 4; ni++) {
            int r  = m0 + wm0 + mi * 16 + gid;
            int cc = n0 + wn0 + ni * 8 + tg2;
            *(float2*)(C + (long)r * N + cc)       = make_float2(c[mi][ni][0], c[mi][ni][1]);
            *(float2*)(C + (long)(r + 8) * N + cc) = make_float2(c[mi][ni][2], c[mi][ni][3]);
        }
    }
}

// ---------------- elementwise kernels ----------------
__global__ void silu_expert_kernel() {
    long i = blockIdx.x * (long)blockDim.x + threadIdx.x;
    long total = (long)g_total * ID;
    if (i < total) {
        int slot = (int)(i / ID);
        int col  = (int)(i % ID);
        float g = g_gubuf[(long)slot * 1024 + col];
        float u = g_gubuf[(long)slot * 1024 + 512 + col];
        g_hbuf[i] = (g / (1.f + expf(-g))) * u;
    }
}

__global__ void silu_shared_kernel(int N) {
    long i = blockIdx.x * (long)blockDim.x + threadIdx.x;
    if (i < (long)N * ISD) {
        float g = g_gbuf[i], u = g_ubuf[i];
        g_gbuf[i] = (g / (1.f + expf(-g))) * u;   // in place
    }
}

__global__ void final_kernel(float* __restrict__ out, int N) {
    long i = blockIdx.x * (long)blockDim.x + threadIdx.x;
    if (i >= (long)N * HD) return;
    int t = (int)(i >> 10);
    int h = (int)(i & (HD - 1));
    int s0 = g_slot_of[t*2], s1 = g_slot_of[t*2 + 1];
    float v = g_shout[i] * g_sgate[t]
            + g_w[t*2]     * g_dres[(long)s0 * HD + h]
            + g_w[t*2 + 1] * g_dres[(long)s1 * HD + h];
    out[i] = v;
}

// ---------------- launch ----------------
extern "C" void kernel_launch(void* const* d_in, const int* in_sizes, int n_in,
                              void* d_out, int out_size) {
    const float* x    = (const float*)d_in[0];
    const float* gw   = (const float*)d_in[1];
    const float* gup  = (const float*)d_in[2];
    const float* down = (const float*)d_in[3];
    const float* sgp  = (const float*)d_in[4];
    const float* sup  = (const float*)d_in[5];
    const float* sdp  = (const float*)d_in[6];
    const float* segw = (const float*)d_in[7];
    float* out = (float*)d_out;
    int N = in_sizes[0] / HD;   // 8192

    float *p_gubuf, *p_hbuf, *p_dres, *p_gbuf, *p_ubuf, *p_shout;
    int *p_tok_idx, *p_blk_e;
    cudaGetSymbolAddress((void**)&p_gubuf,  g_gubuf);
    cudaGetSymbolAddress((void**)&p_hbuf,   g_hbuf);
    cudaGetSymbolAddress((void**)&p_dres,   g_dres);
    cudaGetSymbolAddress((void**)&p_gbuf,   g_gbuf);
    cudaGetSymbolAddress((void**)&p_ubuf,   g_ubuf);
    cudaGetSymbolAddress((void**)&p_shout,  g_shout);
    cudaGetSymbolAddress((void**)&p_tok_idx, g_tok_idx);
    cudaGetSymbolAddress((void**)&p_blk_e,  g_blk_e);

    init_kernel<<<(SLOT_CAP + 255) / 256, 256>>>();
    router_kernel<<<(N + 7) / 8, 256>>>(x, gw, segw, N);
    offsets_kernel<<<1, 32>>>(out, (long)out_size - 1, N);
    assign_kernel<<<(N + 255) / 256, 256>>>(N);

    // expert gate_up: [total_slots, 2I] = gather(x) @ gate_up[e]^T
    gemm_tf32<<<dim3(MTILES, (2 * ID) / 128), 256>>>(
        x, gup, p_gubuf, 0, 2 * ID, HD, p_tok_idx, p_blk_e, (long)(2 * ID) * HD, 1);
    silu_expert_kernel<<<(SLOT_CAP * ID) / 256, 256>>>();
    // expert down: [total_slots, H] = h @ down[e]^T
    gemm_tf32<<<dim3(MTILES, HD / 128), 256>>>(
        p_hbuf, down, p_dres, 0, HD, ID, nullptr, p_blk_e, (long)HD * ID, 1);

    // shared expert
    gemm_tf32<<<dim3(N / 128, ISD / 128), 256>>>(
        x, sgp, p_gbuf, N, ISD, HD, nullptr, nullptr, 0, 0);
    gemm_tf32<<<dim3(N / 128, ISD / 128), 256>>>(
        x, sup, p_ubuf, N, ISD, HD, nullptr, nullptr, 0, 0);
    silu_shared_kernel<<<(int)(((long)N * ISD) / 256), 256>>>(N);
    gemm_tf32<<<dim3(N / 128, HD / 128), 256>>>(
        p_gbuf, sdp, p_shout, N, HD, ISD, nullptr, nullptr, 0, 0);

    final_kernel<<<(int)(((long)N * HD) / 256), 256>>>(out, N);
}

// round 7
// speedup vs baseline: 1.2897x; 1.2897x over previous
#include <cuda_runtime.h>
#include <cstdint>
#include <math.h>

// ---------------- problem constants ----------------
#define NE   16
#define HD   1024
#define ID   512
#define ISD  2048
#define NTOK 8192
#define SLOT_CAP (NTOK*2 + NE*128)   // 18432
#define MTILES   (SLOT_CAP/128)      // 144
#define STAGES   4
#define SMS      136                  // smem row stride (floats); 136%32==8
#define STAGE_FLOATS (16*SMS)         // 2176
#define STAGE_BYTES  (STAGE_FLOATS*4) // 8704
#define SMEM_DYN (STAGES*STAGE_BYTES*2)  // 69632

// ---------------- scratch (device globals) ----------------
__device__ float g_hbuf [(size_t)SLOT_CAP * ID];    // silu(g)*u per slot (tf32-rounded)
__device__ float g_dres [(size_t)SLOT_CAP * HD];    // expert down output
__device__ float g_gbuf [(size_t)NTOK * ISD];       // shared silu(g)*u (tf32-rounded)
__device__ float g_shout[(size_t)NTOK * HD];        // shared down output
__device__ float g_xr   [(size_t)NTOK * HD];        // x rounded to tf32
__device__ float g_gupr [(size_t)NE * 2 * ID * HD]; // interleaved g/u expert weights, rounded
__device__ float g_downr[(size_t)NE * HD * ID];     // rounded
__device__ float g_sgur [(size_t)2 * ISD * HD];     // interleaved shared g/u weights, rounded
__device__ float g_sdpr [(size_t)HD * ISD];         // rounded
__device__ int   g_tok_idx[SLOT_CAP];
__device__ int   g_slot_of[NTOK*2];
__device__ int   g_sel[NTOK*2];
__device__ float g_w[NTOK*2];
__device__ float g_sgate[NTOK];
__device__ int   g_cnt[NE];
__device__ float g_probsum[NE];
__device__ int   g_fill[NE];
__device__ int   g_eoff[NE+1];
__device__ int   g_blk_e[MTILES];
__device__ int   g_total;

// ---------------- helpers ----------------
__device__ __forceinline__ float cvt_tf32(float f) {
    unsigned u;
    asm("cvt.rna.tf32.f32 %0, %1;" : "=r"(u) : "f"(f));
    return __uint_as_float(u);
}

// ---------------- K0: init ----------------
__global__ void init_kernel() {
    int i = blockIdx.x * blockDim.x + threadIdx.x;
    if (i < SLOT_CAP) g_tok_idx[i] = -1;
    if (i < NE) { g_cnt[i] = 0; g_probsum[i] = 0.f; g_fill[i] = 0; }
}

// ---------------- K1: router (one warp per token) ----------------
__global__ void router_kernel(const float* __restrict__ x,
                              const float* __restrict__ gw,
                              const float* __restrict__ segw, int N) {
    int warp = (blockIdx.x * blockDim.x + threadIdx.x) >> 5;
    int lane = threadIdx.x & 31;
    __shared__ float s_ps[NE];
    __shared__ int   s_cnt[NE];
    if (threadIdx.x < NE) { s_ps[threadIdx.x] = 0.f; s_cnt[threadIdx.x] = 0; }
    __syncthreads();

    if (warp < N) {
        float acc[17];
        #pragma unroll
        for (int j = 0; j < 17; j++) acc[j] = 0.f;
        const float* xr = x + (size_t)warp * HD;
        for (int k = lane; k < HD; k += 32) {
            float xv = __ldg(xr + k);
            #pragma unroll
            for (int j = 0; j < NE; j++) acc[j] += xv * __ldg(gw + j * HD + k);
            acc[16] += xv * __ldg(segw + k);
        }
        #pragma unroll
        for (int j = 0; j < 17; j++) {
            #pragma unroll
            for (int o = 16; o > 0; o >>= 1)
                acc[j] += __shfl_xor_sync(0xffffffffu, acc[j], o);
        }
        float mx = acc[0];
        #pragma unroll
        for (int j = 1; j < NE; j++) mx = fmaxf(mx, acc[j]);
        float p[NE]; float s = 0.f;
        #pragma unroll
        for (int j = 0; j < NE; j++) { p[j] = expf(acc[j] - mx); s += p[j]; }
        float inv = 1.f / s;
        #pragma unroll
        for (int j = 0; j < NE; j++) p[j] *= inv;
        int a0 = 0;
        #pragma unroll
        for (int j = 1; j < NE; j++) if (p[j] > p[a0]) a0 = j;
        int a1 = (a0 == 0) ? 1 : 0;
        #pragma unroll
        for (int j = 0; j < NE; j++) if (j != a0 && p[j] > p[a1]) a1 = j;
        float ww = p[a0] + p[a1];
        if (lane == 0) {
            g_sel[warp*2]   = a0;  g_sel[warp*2+1] = a1;
            g_w[warp*2]     = p[a0] / ww;
            g_w[warp*2+1]   = p[a1] / ww;
            g_sgate[warp]   = 1.f / (1.f + expf(-acc[16]));
            atomicAdd(&s_cnt[a0], 1); atomicAdd(&s_cnt[a1], 1);
        }
        if (lane < NE) atomicAdd(&s_ps[lane], p[lane]);
    }
    __syncthreads();
    if (threadIdx.x < NE) {
        atomicAdd(&g_probsum[threadIdx.x], s_ps[threadIdx.x]);
        atomicAdd(&g_cnt[threadIdx.x], s_cnt[threadIdx.x]);
    }
}

// ---------------- K2: offsets + aux loss ----------------
__global__ void offsets_kernel(float* __restrict__ out, long aux_index, int N) {
    if (threadIdx.x == 0 && blockIdx.x == 0) {
        int off = 0;
        for (int e = 0; e < NE; e++) {
            g_eoff[e] = off;
            off += ((g_cnt[e] + 127) / 128) * 128;
        }
        g_eoff[NE] = off;
        g_total = off;
        for (int e = 0; e < NE; e++)
            for (int t = g_eoff[e] / 128; t < g_eoff[e+1] / 128; t++)
                g_blk_e[t] = e;
        float aux = 0.f;
        for (int e = 0; e < NE; e++)
            aux += ((float)g_cnt[e] / (float)(N * 2)) * (g_probsum[e] / (float)N);
        out[aux_index] = (float)NE * aux;
    }
}

// ---------------- K3: slot assignment ----------------
__global__ void assign_kernel(int N) {
    int t = blockIdx.x * blockDim.x + threadIdx.x;
    if (t < N) {
        #pragma unroll
        for (int i = 0; i < 2; i++) {
            int e = g_sel[t*2 + i];
            int pos = atomicAdd(&g_fill[e], 1);
            int slot = g_eoff[e] + pos;
            g_tok_idx[slot] = t;
            g_slot_of[t*2 + i] = slot;
        }
    }
}

// ---------------- conversion kernels (fp32 -> tf32-RNA copies) ----------------
__global__ void round_copy4(const float4* __restrict__ src, float4* __restrict__ dst, long n4) {
    long i = blockIdx.x * (long)blockDim.x + threadIdx.x;
    if (i < n4) {
        float4 v = src[i];
        v.x = cvt_tf32(v.x); v.y = cvt_tf32(v.y);
        v.z = cvt_tf32(v.z); v.w = cvt_tf32(v.w);
        dst[i] = v;
    }
}

// gup [E][2I][H] -> interleaved: dst row 2j = gate_j, 2j+1 = up_j (per expert)
__global__ void interleave_gup_kernel(const float* __restrict__ src, float* __restrict__ dst) {
    long i4 = blockIdx.x * (long)blockDim.x + threadIdx.x;
    long total4 = (long)NE * 2 * ID * HD / 4;
    if (i4 >= total4) return;
    long i = i4 * 4;
    long e = i >> 20;
    int  r = (int)((i >> 10) & 1023);
    int  k = (int)(i & 1023);
    int  j = r >> 1;
    int  sr = (r & 1) ? (ID + j) : j;
    float4 v = *(const float4*)(src + (e << 20) + (size_t)sr * HD + k);
    v.x = cvt_tf32(v.x); v.y = cvt_tf32(v.y); v.z = cvt_tf32(v.z); v.w = cvt_tf32(v.w);
    *(float4*)(dst + i) = v;
}

// sgp/sup [IS][H] -> interleaved [2*IS][H]: row 2j = sgp_j, 2j+1 = sup_j
__global__ void interleave_sgu_kernel(const float* __restrict__ g, const float* __restrict__ u,
                                      float* __restrict__ dst) {
    long i4 = blockIdx.x * (long)blockDim.x + threadIdx.x;
    long total4 = (long)2 * ISD * HD / 4;
    if (i4 >= total4) return;
    long i = i4 * 4;
    int r = (int)(i >> 10);
    int k = (int)(i & 1023);
    int j = r >> 1;
    const float* s = (r & 1) ? u : g;
    float4 v = *(const float4*)(s + (size_t)j * HD + k);
    v.x = cvt_tf32(v.x); v.y = cvt_tf32(v.y); v.z = cvt_tf32(v.z); v.w = cvt_tf32(v.w);
    *(float4*)(dst + i) = v;
}

// ---------------- mma.sync tf32 GEMM: C[M,N] = A[M,K] @ B[N,K]^T ----------------
// Tile 128x128, K-step 16. 4-stage cp.async pipeline (4B zfill copies) into
// transposed [k][m] smem (stride 136, +2*(k>>2) lane shift: conflict-free STS+LDS).
// Inputs must be tf32-pre-rounded. 2 CTAs/SM.
// row_map: optional gather for A rows (-1 => zero row).
// blk_e:   per-m-tile expert selection for B (+ e*estride).
// fuse_silu: C cols are interleaved (g,u) -> write cvt_tf32(silu(g)*u) at col/2.
__global__ __launch_bounds__(256, 2)
void gemm_tf32(const float* __restrict__ A, const float* __restrict__ B,
               float* __restrict__ C, int K, int ldc,
               const int* __restrict__ row_map,
               const int* __restrict__ blk_e, long estride,
               int fuse_silu, int m_from_dev)
{
    const int M = m_from_dev ? g_total : (int)(gridDim.x * 128);
    const int m0 = blockIdx.x * 128;
    if (m0 >= M) return;
    const int n0 = blockIdx.y * 128;

    extern __shared__ float dsm[];
    const uint32_t sA = (uint32_t)__cvta_generic_to_shared(dsm);
    const uint32_t sB = sA + STAGES * STAGE_BYTES;
    float* dsmB = dsm + STAGES * STAGE_FLOATS;

    const int t    = threadIdx.x;
    const int lane = t & 31;
    const int wid  = t >> 5;
    const int wm0  = (wid & 1) * 64;
    const int wn0  = (wid >> 1) * 32;
    const int kcol = t & 15;       // k within tile owned by this thread
    const int mcol = t >> 4;       // base row (0..15); rows mcol+16j, j=0..7

    const char* Ab = (const char*)A;
    const char* Bb = (const char*)(blk_e ? (B + (size_t)__ldg(&blk_e[blockIdx.x]) * estride) : B);

    unsigned aoff[8], boff[8]; int asz[8];
    #pragma unroll
    for (int j = 0; j < 8; j++) {
        int m = mcol + 16 * j;
        if (row_map) {
            int tok = __ldg(&row_map[m0 + m]);
            asz[j]  = (tok < 0) ? 0 : 4;
            aoff[j] = (unsigned)((tok < 0 ? 0 : tok) * K) * 4u;
        } else {
            asz[j]  = 4;
            aoff[j] = (unsigned)((m0 + m) * K) * 4u;
        }
        boff[j] = (unsigned)((n0 + m) * K) * 4u;
    }
    // smem write offset for this thread (bytes), within a stage
    const uint32_t woff = (uint32_t)(kcol * SMS + 2 * (kcol >> 2) + mcol) * 4u;

    const int KT = K >> 4;

    float c[4][4][4];
    #pragma unroll
    for (int mi = 0; mi < 4; mi++)
        #pragma unroll
        for (int ni = 0; ni < 4; ni++)
            #pragma unroll
            for (int q = 0; q < 4; q++) c[mi][ni][q] = 0.f;

    auto fetch = [&](int kt_f) {
        int slot = kt_f & 3;
        uint32_t aD = sA + slot * STAGE_BYTES + woff;
        uint32_t bD = sB + slot * STAGE_BYTES + woff;
        unsigned koff = (unsigned)kt_f * 64u + (unsigned)kcol * 4u;
        #pragma unroll
        for (int j = 0; j < 8; j++) {
            asm volatile("cp.async.ca.shared.global [%0], [%1], 4, %2;"
                         :: "r"(aD + j * 64), "l"(Ab + aoff[j] + koff), "r"(asz[j]));
            asm volatile("cp.async.ca.shared.global [%0], [%1], 4, 4;"
                         :: "r"(bD + j * 64), "l"(Bb + boff[j] + koff));
        }
    };

    // prologue: stages 0..2
    #pragma unroll
    for (int s = 0; s < STAGES - 1; s++) {
        if (s < KT) fetch(s);
        asm volatile("cp.async.commit_group;");
    }

    const int tg  = lane & 3;
    const int gid = lane >> 2;

    for (int kt = 0; kt < KT; kt++) {
        asm volatile("cp.async.wait_group %0;" :: "n"(STAGES - 2));
        __syncthreads();    // stage kt ready; all warps done with compute(kt-1)
        int ft = kt + STAGES - 1;
        if (ft < KT) fetch(ft);
        asm volatile("cp.async.commit_group;");

        const int slot = kt & 3;
        const float* Sa = dsm  + slot * STAGE_FLOATS;
        const float* Sb = dsmB + slot * STAGE_FLOATS;
        #pragma unroll
        for (int ks = 0; ks < 2; ks++) {
            const int kk = ks * 8;
            const int sh_lo = ks * 4;       // 2*((kk+tg)>>2)
            const int sh_hi = 2 + ks * 4;   // 2*((kk+4+tg)>>2)
            const float* Alo = Sa + (kk + tg)     * SMS + sh_lo;
            const float* Ahi = Sa + (kk + 4 + tg) * SMS + sh_hi;
            const float* Blo = Sb + (kk + tg)     * SMS + sh_lo;
            const float* Bhi = Sb + (kk + 4 + tg) * SMS + sh_hi;
            unsigned a[4][4], b[4][2];
            #pragma unroll
            for (int mi = 0; mi < 4; mi++) {
                int m = wm0 + mi * 16 + gid;
                a[mi][0] = __float_as_uint(Alo[m]);
                a[mi][1] = __float_as_uint(Alo[m + 8]);
                a[mi][2] = __float_as_uint(Ahi[m]);
                a[mi][3] = __float_as_uint(Ahi[m + 8]);
            }
            #pragma unroll
            for (int ni = 0; ni < 4; ni++) {
                int n = wn0 + ni * 8 + gid;
                b[ni][0] = __float_as_uint(Blo[n]);
                b[ni][1] = __float_as_uint(Bhi[n]);
            }
            #pragma unroll
            for (int mi = 0; mi < 4; mi++)
                #pragma unroll
                for (int ni = 0; ni < 4; ni++)
                    asm volatile(
                        "mma.sync.aligned.m16n8k8.row.col.f32.tf32.tf32.f32 "
                        "{%0,%1,%2,%3}, {%4,%5,%6,%7}, {%8,%9}, {%0,%1,%2,%3};\n"
                        : "+f"(c[mi][ni][0]), "+f"(c[mi][ni][1]),
                          "+f"(c[mi][ni][2]), "+f"(c[mi][ni][3])
                        : "r"(a[mi][0]), "r"(a[mi][1]), "r"(a[mi][2]), "r"(a[mi][3]),
                          "r"(b[ni][0]), "r"(b[ni][1]));
        }
    }

    // epilogue
    const int tg2 = (lane & 3) * 2;
    if (fuse_silu) {
        #pragma unroll
        for (int mi = 0; mi < 4; mi++) {
            int r = m0 + wm0 + mi * 16 + gid;
            #pragma unroll
            for (int ni = 0; ni < 4; ni++) {
                int cc = (n0 + wn0 + ni * 8 + tg2) >> 1;   // output channel
                float g0 = c[mi][ni][0], u0 = c[mi][ni][1];
                float g1 = c[mi][ni][2], u1 = c[mi][ni][3];
                float h0 = (g0 / (1.f + __expf(-g0))) * u0;
                float h1 = (g1 / (1.f + __expf(-g1))) * u1;
                C[(size_t)r * ldc + cc]       = cvt_tf32(h0);
                C[(size_t)(r + 8) * ldc + cc] = cvt_tf32(h1);
            }
        }
    } else {
        #pragma unroll
        for (int mi = 0; mi < 4; mi++) {
            #pragma unroll
            for (int ni = 0; ni < 4; ni++) {
                int r  = m0 + wm0 + mi * 16 + gid;
                int cc = n0 + wn0 + ni * 8 + tg2;
                *(float2*)(C + (size_t)r * ldc + cc)       = make_float2(c[mi][ni][0], c[mi][ni][1]);
                *(float2*)(C + (size_t)(r + 8) * ldc + cc) = make_float2(c[mi][ni][2], c[mi][ni][3]);
            }
        }
    }
}

// ---------------- final combine ----------------
__global__ void final_kernel(float* __restrict__ out, int N) {
    long i = blockIdx.x * (long)blockDim.x + threadIdx.x;
    if (i >= (long)N * HD) return;
    int t = (int)(i >> 10);
    int h = (int)(i & (HD - 1));
    int s0 = g_slot_of[t*2], s1 = g_slot_of[t*2 + 1];
    float v = g_shout[i] * g_sgate[t]
            + g_w[t*2]     * g_dres[(size_t)s0 * HD + h]
            + g_w[t*2 + 1] * g_dres[(size_t)s1 * HD + h];
    out[i] = v;
}

// ---------------- launch ----------------
extern "C" void kernel_launch(void* const* d_in, const int* in_sizes, int n_in,
                              void* d_out, int out_size) {
    const float* x    = (const float*)d_in[0];
    const float* gw   = (const float*)d_in[1];
    const float* gup  = (const float*)d_in[2];
    const float* down = (const float*)d_in[3];
    const float* sgp  = (const float*)d_in[4];
    const float* sup  = (const float*)d_in[5];
    const float* sdp  = (const float*)d_in[6];
    const float* segw = (const float*)d_in[7];
    float* out = (float*)d_out;
    int N = in_sizes[0] / HD;   // 8192

    float *p_hbuf, *p_dres, *p_gbuf, *p_shout, *p_xr, *p_gupr, *p_downr, *p_sgur, *p_sdpr;
    int *p_tok_idx, *p_blk_e;
    cudaGetSymbolAddress((void**)&p_hbuf,   g_hbuf);
    cudaGetSymbolAddress((void**)&p_dres,   g_dres);
    cudaGetSymbolAddress((void**)&p_gbuf,   g_gbuf);
    cudaGetSymbolAddress((void**)&p_shout,  g_shout);
    cudaGetSymbolAddress((void**)&p_xr,     g_xr);
    cudaGetSymbolAddress((void**)&p_gupr,   g_gupr);
    cudaGetSymbolAddress((void**)&p_downr,  g_downr);
    cudaGetSymbolAddress((void**)&p_sgur,   g_sgur);
    cudaGetSymbolAddress((void**)&p_sdpr,   g_sdpr);
    cudaGetSymbolAddress((void**)&p_tok_idx, g_tok_idx);
    cudaGetSymbolAddress((void**)&p_blk_e,  g_blk_e);

    static int attr_done = 0;
    if (!attr_done) {
        cudaFuncSetAttribute(gemm_tf32, cudaFuncAttributeMaxDynamicSharedMemorySize, SMEM_DYN);
        attr_done = 1;
    }

    init_kernel<<<(SLOT_CAP + 255) / 256, 256>>>();
    router_kernel<<<(N + 7) / 8, 256>>>(x, gw, segw, N);
    offsets_kernel<<<1, 32>>>(out, (long)out_size - 1, N);
    assign_kernel<<<(N + 255) / 256, 256>>>(N);

    // conversions (tf32-RNA pre-rounding; g/u row interleaving for fused silu)
    interleave_gup_kernel<<<(int)((long)NE*2*ID*HD/4/256), 256>>>(gup, p_gupr);
    round_copy4<<<(int)((long)NE*HD*ID/4/256), 256>>>((const float4*)down, (float4*)p_downr,
                                                      (long)NE*HD*ID/4);
    interleave_sgu_kernel<<<(int)((long)2*ISD*HD/4/256), 256>>>(sgp, sup, p_sgur);
    round_copy4<<<(int)((long)HD*ISD/4/256), 256>>>((const float4*)sdp, (float4*)p_sdpr,
                                                    (long)HD*ISD/4);
    round_copy4<<<(int)((long)N*HD/4/256), 256>>>((const float4*)x, (float4*)p_xr,
                                                  (long)N*HD/4);

    // expert gate_up (fused silu): hbuf[slot][512] from gathered x
    gemm_tf32<<<dim3(MTILES, 8), 256, SMEM_DYN>>>(
        p_xr, p_gupr, p_hbuf, HD, ID, p_tok_idx, p_blk_e, (long)2*ID*HD, 1, 1);
    // expert down: dres[slot][1024]
    gemm_tf32<<<dim3(MTILES, 8), 256, SMEM_DYN>>>(
        p_hbuf, p_downr, p_dres, ID, HD, nullptr, p_blk_e, (long)HD*ID, 0, 1);
    // shared gate/up (fused silu): gbuf[token][2048]
    gemm_tf32<<<dim3(N/128, 32), 256, SMEM_DYN>>>(
        p_xr, p_sgur, p_gbuf, HD, ISD, nullptr, nullptr, 0, 1, 0);
    // shared down: shout[token][1024]
    gemm_tf32<<<dim3(N/128, 8), 256, SMEM_DYN>>>(
        p_gbuf, p_sdpr, p_shout, ISD, HD, nullptr, nullptr, 0, 0, 0);

    final_kernel<<<(int)(((long)N * HD) / 256), 256>>>(out, N);
}

// round 8
// speedup vs baseline: 1.7933x; 1.3904x over previous
#include <cuda_runtime.h>
#include <cstdint>
#include <math.h>

// ---------------- problem constants ----------------
#define NE   16
#define HD   1024
#define ID   512
#define ISD  2048
#define NTOK 8192
#define SLOT_CAP (NTOK*2 + NE*128)   // 18432
#define MTILES   (SLOT_CAP/128)      // 144
#define STAGES   4
#define P        20                   // smem row stride in floats (conflict-free)
#define A_FLOATS (128*P)              // 2560
#define B_FLOATS (256*P)              // 5120
#define STG_FLOATS (A_FLOATS + B_FLOATS)  // 7680
#define STG_BYTES  (STG_FLOATS*4)         // 30720
#define SMEM_DYN   (STAGES*STG_BYTES)     // 122880

// ---------------- scratch (device globals) ----------------
__device__ float g_hbuf [(size_t)SLOT_CAP * ID];    // silu(g)*u per slot (tf32-rounded)
__device__ float g_dres [(size_t)SLOT_CAP * HD];    // expert down output
__device__ float g_gbuf [(size_t)NTOK * ISD];       // shared silu(g)*u (tf32-rounded)
__device__ float g_xr   [(size_t)NTOK * HD];        // x rounded to tf32
__device__ float g_gupr [(size_t)NE * 2 * ID * HD]; // interleaved g/u expert weights, rounded
__device__ float g_downr[(size_t)NE * HD * ID];     // rounded
__device__ float g_sgur [(size_t)2 * ISD * HD];     // interleaved shared g/u weights, rounded
__device__ float g_sdpr [(size_t)HD * ISD];         // rounded
__device__ int   g_tok_idx[SLOT_CAP];
__device__ int   g_slot_of[NTOK*2];
__device__ int   g_sel[NTOK*2];
__device__ float g_w[NTOK*2];
__device__ float g_sgate[NTOK];
__device__ int   g_cnt[NE];
__device__ float g_probsum[NE];
__device__ int   g_fill[NE];
__device__ int   g_eoff[NE+1];
__device__ int   g_blk_e[MTILES];
__device__ int   g_total;

// ---------------- helpers ----------------
__device__ __forceinline__ float cvt_tf32(float f) {
    unsigned u;
    asm("cvt.rna.tf32.f32 %0, %1;" : "=r"(u) : "f"(f));
    return __uint_as_float(u);
}

// ---------------- K0: init ----------------
__global__ void init_kernel() {
    int i = blockIdx.x * blockDim.x + threadIdx.x;
    if (i < SLOT_CAP) g_tok_idx[i] = -1;
    if (i < NE) { g_cnt[i] = 0; g_probsum[i] = 0.f; g_fill[i] = 0; }
}

// ---------------- K1: router (one warp per token) ----------------
__global__ void router_kernel(const float* __restrict__ x,
                              const float* __restrict__ gw,
                              const float* __restrict__ segw, int N) {
    int warp = (blockIdx.x * blockDim.x + threadIdx.x) >> 5;
    int lane = threadIdx.x & 31;
    __shared__ float s_ps[NE];
    __shared__ int   s_cnt[NE];
    if (threadIdx.x < NE) { s_ps[threadIdx.x] = 0.f; s_cnt[threadIdx.x] = 0; }
    __syncthreads();

    if (warp < N) {
        float acc[17];
        #pragma unroll
        for (int j = 0; j < 17; j++) acc[j] = 0.f;
        const float* xr = x + (size_t)warp * HD;
        for (int k = lane; k < HD; k += 32) {
            float xv = __ldg(xr + k);
            #pragma unroll
            for (int j = 0; j < NE; j++) acc[j] += xv * __ldg(gw + j * HD + k);
            acc[16] += xv * __ldg(segw + k);
        }
        #pragma unroll
        for (int j = 0; j < 17; j++) {
            #pragma unroll
            for (int o = 16; o > 0; o >>= 1)
                acc[j] += __shfl_xor_sync(0xffffffffu, acc[j], o);
        }
        float mx = acc[0];
        #pragma unroll
        for (int j = 1; j < NE; j++) mx = fmaxf(mx, acc[j]);
        float p[NE]; float s = 0.f;
        #pragma unroll
        for (int j = 0; j < NE; j++) { p[j] = expf(acc[j] - mx); s += p[j]; }
        float inv = 1.f / s;
        #pragma unroll
        for (int j = 0; j < NE; j++) p[j] *= inv;
        int a0 = 0;
        #pragma unroll
        for (int j = 1; j < NE; j++) if (p[j] > p[a0]) a0 = j;
        int a1 = (a0 == 0) ? 1 : 0;
        #pragma unroll
        for (int j = 0; j < NE; j++) if (j != a0 && p[j] > p[a1]) a1 = j;
        float ww = p[a0] + p[a1];
        if (lane == 0) {
            g_sel[warp*2]   = a0;  g_sel[warp*2+1] = a1;
            g_w[warp*2]     = p[a0] / ww;
            g_w[warp*2+1]   = p[a1] / ww;
            g_sgate[warp]   = 1.f / (1.f + expf(-acc[16]));
            atomicAdd(&s_cnt[a0], 1); atomicAdd(&s_cnt[a1], 1);
        }
        if (lane < NE) atomicAdd(&s_ps[lane], p[lane]);
    }
    __syncthreads();
    if (threadIdx.x < NE) {
        atomicAdd(&g_probsum[threadIdx.x], s_ps[threadIdx.x]);
        atomicAdd(&g_cnt[threadIdx.x], s_cnt[threadIdx.x]);
    }
}

// ---------------- K2: offsets + aux loss ----------------
__global__ void offsets_kernel(float* __restrict__ out, long aux_index, int N) {
    if (threadIdx.x == 0 && blockIdx.x == 0) {
        int off = 0;
        for (int e = 0; e < NE; e++) {
            g_eoff[e] = off;
            off += ((g_cnt[e] + 127) / 128) * 128;
        }
        g_eoff[NE] = off;
        g_total = off;
        for (int e = 0; e < NE; e++)
            for (int t = g_eoff[e] / 128; t < g_eoff[e+1] / 128; t++)
                g_blk_e[t] = e;
        float aux = 0.f;
        for (int e = 0; e < NE; e++)
            aux += ((float)g_cnt[e] / (float)(N * 2)) * (g_probsum[e] / (float)N);
        out[aux_index] = (float)NE * aux;
    }
}

// ---------------- K3: slot assignment ----------------
__global__ void assign_kernel(int N) {
    int t = blockIdx.x * blockDim.x + threadIdx.x;
    if (t < N) {
        #pragma unroll
        for (int i = 0; i < 2; i++) {
            int e = g_sel[t*2 + i];
            int pos = atomicAdd(&g_fill[e], 1);
            int slot = g_eoff[e] + pos;
            g_tok_idx[slot] = t;
            g_slot_of[t*2 + i] = slot;
        }
    }
}

// ---------------- conversion kernels (fp32 -> tf32-RNA copies) ----------------
__global__ void round_copy4(const float4* __restrict__ src, float4* __restrict__ dst, long n4) {
    long i = blockIdx.x * (long)blockDim.x + threadIdx.x;
    if (i < n4) {
        float4 v = src[i];
        v.x = cvt_tf32(v.x); v.y = cvt_tf32(v.y);
        v.z = cvt_tf32(v.z); v.w = cvt_tf32(v.w);
        dst[i] = v;
    }
}

// gup [E][2I][H] -> interleaved: dst row 2j = gate_j, 2j+1 = up_j (per expert)
__global__ void interleave_gup_kernel(const float* __restrict__ src, float* __restrict__ dst) {
    long i4 = blockIdx.x * (long)blockDim.x + threadIdx.x;
    long total4 = (long)NE * 2 * ID * HD / 4;
    if (i4 >= total4) return;
    long i = i4 * 4;
    long e = i >> 20;
    int  r = (int)((i >> 10) & 1023);
    int  k = (int)(i & 1023);
    int  j = r >> 1;
    int  sr = (r & 1) ? (ID + j) : j;
    float4 v = *(const float4*)(src + (e << 20) + (size_t)sr * HD + k);
    v.x = cvt_tf32(v.x); v.y = cvt_tf32(v.y); v.z = cvt_tf32(v.z); v.w = cvt_tf32(v.w);
    *(float4*)(dst + i) = v;
}

// sgp/sup [IS][H] -> interleaved [2*IS][H]: row 2j = sgp_j, 2j+1 = sup_j
__global__ void interleave_sgu_kernel(const float* __restrict__ g, const float* __restrict__ u,
                                      float* __restrict__ dst) {
    long i4 = blockIdx.x * (long)blockDim.x + threadIdx.x;
    long total4 = (long)2 * ISD * HD / 4;
    if (i4 >= total4) return;
    long i = i4 * 4;
    int r = (int)(i >> 10);
    int k = (int)(i & 1023);
    int j = r >> 1;
    const float* s = (r & 1) ? u : g;
    float4 v = *(const float4*)(s + (size_t)j * HD + k);
    v.x = cvt_tf32(v.x); v.y = cvt_tf32(v.y); v.z = cvt_tf32(v.z); v.w = cvt_tf32(v.w);
    *(float4*)(dst + i) = v;
}

// ---------------- mma.sync tf32 GEMM: C[M,N] = A[M,K] @ B[N,K]^T ----------------
// CTA tile 128x256, warp tile 64x64, K-step 16. 4-stage 16B-cp.async pipeline,
// row-major smem [row][16] with stride P=20 (conflict-free stores + fragment LDS).
// Inputs must be tf32-pre-rounded.
// row_map: optional gather for A rows (-1 => zero row).
// blk_e:   per-m-tile expert selection for B (+ e*estride).
// mode: 0 = plain store; 1 = fused silu on interleaved (g,u) cols -> C[.][col/2];
//       2 = fused final combine: C = c*sgate + w0*dres[s0] + w1*dres[s1].
__global__ __launch_bounds__(256, 1)
void gemm_tf32(const float* __restrict__ A, const float* __restrict__ B,
               float* __restrict__ C, int K, int ldc,
               const int* __restrict__ row_map,
               const int* __restrict__ blk_e, long estride,
               int mode, int m_from_dev)
{
    const int M = m_from_dev ? g_total : (int)(gridDim.x * 128);
    const int m0 = blockIdx.x * 128;
    if (m0 >= M) return;
    const int n0 = blockIdx.y * 256;

    extern __shared__ float dsm[];
    const uint32_t sbase = (uint32_t)__cvta_generic_to_shared(dsm);

    const int t    = threadIdx.x;
    const int lane = t & 31;
    const int wid  = t >> 5;
    const int wm0  = (wid & 1) * 64;
    const int wn0  = (wid >> 1) * 64;
    const int tg   = lane & 3;
    const int gid  = lane >> 2;

    // ---- fetch mapping: each thread owns A row (t&127) and B rows (t&127, +128),
    //      2 16B chunks each at cols half*8 + {0,4}
    const int frow = t & 127;
    const int c0   = (t >> 7) * 8;
    const float* aptr;
    unsigned asz;
    if (row_map) {
        int tok = __ldg(&row_map[m0 + frow]);
        asz  = (tok < 0) ? 0u : 16u;
        aptr = A + (size_t)(tok < 0 ? 0 : tok) * K;
    } else {
        asz  = 16u;
        aptr = A + (size_t)(m0 + frow) * K;
    }
    const float* Bp = blk_e ? (B + (size_t)__ldg(&blk_e[blockIdx.x]) * estride) : B;
    const float* bptr0 = Bp + (size_t)(n0 + frow) * K;
    const float* bptr1 = Bp + (size_t)(n0 + frow + 128) * K;

    const uint32_t aDst  = sbase + (uint32_t)(frow * P + c0) * 4u;
    const uint32_t bDst0 = sbase + (uint32_t)(A_FLOATS + frow * P + c0) * 4u;
    const uint32_t bDst1 = sbase + (uint32_t)(A_FLOATS + (frow + 128) * P + c0) * 4u;

    const int KT = K >> 4;

    float c[4][8][4];
    #pragma unroll
    for (int mi = 0; mi < 4; mi++)
        #pragma unroll
        for (int ni = 0; ni < 8; ni++)
            #pragma unroll
            for (int q = 0; q < 4; q++) c[mi][ni][q] = 0.f;

    auto fetch = [&](int kt_f) {
        uint32_t st = (uint32_t)(kt_f & (STAGES - 1)) * STG_BYTES;
        unsigned koff = (unsigned)(kt_f * 16 + c0);
        asm volatile("cp.async.cg.shared.global [%0], [%1], 16, %2;"
                     :: "r"(aDst + st), "l"(aptr + koff), "r"(asz));
        asm volatile("cp.async.cg.shared.global [%0], [%1], 16, %2;"
                     :: "r"(aDst + st + 16), "l"(aptr + koff + 4), "r"(asz));
        asm volatile("cp.async.cg.shared.global [%0], [%1], 16, 16;"
                     :: "r"(bDst0 + st), "l"(bptr0 + koff));
        asm volatile("cp.async.cg.shared.global [%0], [%1], 16, 16;"
                     :: "r"(bDst0 + st + 16), "l"(bptr0 + koff + 4));
        asm volatile("cp.async.cg.shared.global [%0], [%1], 16, 16;"
                     :: "r"(bDst1 + st), "l"(bptr1 + koff));
        asm volatile("cp.async.cg.shared.global [%0], [%1], 16, 16;"
                     :: "r"(bDst1 + st + 16), "l"(bptr1 + koff + 4));
    };

    #pragma unroll
    for (int s = 0; s < STAGES - 1; s++) {
        fetch(s);                     // KT >= 32 always, no bound check needed
        asm volatile("cp.async.commit_group;");
    }

    for (int kt = 0; kt < KT; kt++) {
        asm volatile("cp.async.wait_group %0;" :: "n"(STAGES - 2));
        __syncthreads();
        int ft = kt + STAGES - 1;
        if (ft < KT) fetch(ft);
        asm volatile("cp.async.commit_group;");

        const float* Sa = dsm + (kt & (STAGES - 1)) * STG_FLOATS;
        const float* Sb = Sa + A_FLOATS;
        #pragma unroll
        for (int ks = 0; ks < 2; ks++) {
            const int kk = ks * 8;
            unsigned a[4][4], b[8][2];
            #pragma unroll
            for (int mi = 0; mi < 4; mi++) {
                int m = wm0 + mi * 16 + gid;
                a[mi][0] = __float_as_uint(Sa[m * P + kk + tg]);
                a[mi][1] = __float_as_uint(Sa[(m + 8) * P + kk + tg]);
                a[mi][2] = __float_as_uint(Sa[m * P + kk + 4 + tg]);
                a[mi][3] = __float_as_uint(Sa[(m + 8) * P + kk + 4 + tg]);
            }
            #pragma unroll
            for (int ni = 0; ni < 8; ni++) {
                int n = wn0 + ni * 8 + gid;
                b[ni][0] = __float_as_uint(Sb[n * P + kk + tg]);
                b[ni][1] = __float_as_uint(Sb[n * P + kk + 4 + tg]);
            }
            #pragma unroll
            for (int mi = 0; mi < 4; mi++)
                #pragma unroll
                for (int ni = 0; ni < 8; ni++)
                    asm volatile(
                        "mma.sync.aligned.m16n8k8.row.col.f32.tf32.tf32.f32 "
                        "{%0,%1,%2,%3}, {%4,%5,%6,%7}, {%8,%9}, {%0,%1,%2,%3};\n"
                        : "+f"(c[mi][ni][0]), "+f"(c[mi][ni][1]),
                          "+f"(c[mi][ni][2]), "+f"(c[mi][ni][3])
                        : "r"(a[mi][0]), "r"(a[mi][1]), "r"(a[mi][2]), "r"(a[mi][3]),
                          "r"(b[ni][0]), "r"(b[ni][1]));
        }
    }

    // ---------------- epilogue ----------------
    const int tg2 = tg * 2;
    if (mode == 1) {                      // fused silu: cols are (g,u) pairs
        #pragma unroll
        for (int mi = 0; mi < 4; mi++) {
            int r = m0 + wm0 + mi * 16 + gid;
            #pragma unroll
            for (int ni = 0; ni < 8; ni++) {
                int cc = (n0 + wn0 + ni * 8 + tg2) >> 1;
                float g0 = c[mi][ni][0], u0 = c[mi][ni][1];
                float g1 = c[mi][ni][2], u1 = c[mi][ni][3];
                float h0 = (g0 / (1.f + __expf(-g0))) * u0;
                float h1 = (g1 / (1.f + __expf(-g1))) * u1;
                C[(size_t)r * ldc + cc]       = cvt_tf32(h0);
                C[(size_t)(r + 8) * ldc + cc] = cvt_tf32(h1);
            }
        }
    } else if (mode == 2) {               // fused final combine
        #pragma unroll
        for (int mi = 0; mi < 4; mi++) {
            int r0 = m0 + wm0 + mi * 16 + gid;
            int r1 = r0 + 8;
            float w00 = g_w[2*r0], w01 = g_w[2*r0+1], sg0 = g_sgate[r0];
            int   s00 = g_slot_of[2*r0], s01 = g_slot_of[2*r0+1];
            float w10 = g_w[2*r1], w11 = g_w[2*r1+1], sg1 = g_sgate[r1];
            int   s10 = g_slot_of[2*r1], s11 = g_slot_of[2*r1+1];
            #pragma unroll
            for (int ni = 0; ni < 8; ni++) {
                int cc = n0 + wn0 + ni * 8 + tg2;
                float2 d00 = *(const float2*)&g_dres[(size_t)s00 * HD + cc];
                float2 d01 = *(const float2*)&g_dres[(size_t)s01 * HD + cc];
                float2 o0;
                o0.x = c[mi][ni][0] * sg0 + w00 * d00.x + w01 * d01.x;
                o0.y = c[mi][ni][1] * sg0 + w00 * d00.y + w01 * d01.y;
                *(float2*)(C + (size_t)r0 * ldc + cc) = o0;
                float2 d10 = *(const float2*)&g_dres[(size_t)s10 * HD + cc];
                float2 d11 = *(const float2*)&g_dres[(size_t)s11 * HD + cc];
                float2 o1;
                o1.x = c[mi][ni][2] * sg1 + w10 * d10.x + w11 * d11.x;
                o1.y = c[mi][ni][3] * sg1 + w10 * d10.y + w11 * d11.y;
                *(float2*)(C + (size_t)r1 * ldc + cc) = o1;
            }
        }
    } else {                              // plain
        #pragma unroll
        for (int mi = 0; mi < 4; mi++) {
            #pragma unroll
            for (int ni = 0; ni < 8; ni++) {
                int r  = m0 + wm0 + mi * 16 + gid;
                int cc = n0 + wn0 + ni * 8 + tg2;
                *(float2*)(C + (size_t)r * ldc + cc)       = make_float2(c[mi][ni][0], c[mi][ni][1]);
                *(float2*)(C + (size_t)(r + 8) * ldc + cc) = make_float2(c[mi][ni][2], c[mi][ni][3]);
            }
        }
    }
}

// ---------------- launch ----------------
extern "C" void kernel_launch(void* const* d_in, const int* in_sizes, int n_in,
                              void* d_out, int out_size) {
    const float* x    = (const float*)d_in[0];
    const float* gw   = (const float*)d_in[1];
    const float* gup  = (const float*)d_in[2];
    const float* down = (const float*)d_in[3];
    const float* sgp  = (const float*)d_in[4];
    const float* sup  = (const float*)d_in[5];
    const float* sdp  = (const float*)d_in[6];
    const float* segw = (const float*)d_in[7];
    float* out = (float*)d_out;
    int N = in_sizes[0] / HD;   // 8192

    float *p_hbuf, *p_dres, *p_gbuf, *p_xr, *p_gupr, *p_downr, *p_sgur, *p_sdpr;
    int *p_tok_idx, *p_blk_e;
    cudaGetSymbolAddress((void**)&p_hbuf,   g_hbuf);
    cudaGetSymbolAddress((void**)&p_dres,   g_dres);
    cudaGetSymbolAddress((void**)&p_gbuf,   g_gbuf);
    cudaGetSymbolAddress((void**)&p_xr,     g_xr);
    cudaGetSymbolAddress((void**)&p_gupr,   g_gupr);
    cudaGetSymbolAddress((void**)&p_downr,  g_downr);
    cudaGetSymbolAddress((void**)&p_sgur,   g_sgur);
    cudaGetSymbolAddress((void**)&p_sdpr,   g_sdpr);
    cudaGetSymbolAddress((void**)&p_tok_idx, g_tok_idx);
    cudaGetSymbolAddress((void**)&p_blk_e,  g_blk_e);

    static int attr_done = 0;
    if (!attr_done) {
        cudaFuncSetAttribute(gemm_tf32, cudaFuncAttributeMaxDynamicSharedMemorySize, SMEM_DYN);
        attr_done = 1;
    }

    init_kernel<<<(SLOT_CAP + 255) / 256, 256>>>();
    router_kernel<<<(N + 7) / 8, 256>>>(x, gw, segw, N);
    offsets_kernel<<<1, 32>>>(out, (long)out_size - 1, N);
    assign_kernel<<<(N + 255) / 256, 256>>>(N);

    // conversions (tf32-RNA pre-rounding; g/u row interleaving for fused silu)
    interleave_gup_kernel<<<(int)((long)NE*2*ID*HD/4/256), 256>>>(gup, p_gupr);
    round_copy4<<<(int)((long)NE*HD*ID/4/256), 256>>>((const float4*)down, (float4*)p_downr,
                                                      (long)NE*HD*ID/4);
    interleave_sgu_kernel<<<(int)((long)2*ISD*HD/4/256), 256>>>(sgp, sup, p_sgur);
    round_copy4<<<(int)((long)HD*ISD/4/256), 256>>>((const float4*)sdp, (float4*)p_sdpr,
                                                    (long)HD*ISD/4);
    round_copy4<<<(int)((long)N*HD/4/256), 256>>>((const float4*)x, (float4*)p_xr,
                                                  (long)N*HD/4);

    // expert gate_up (fused silu): hbuf[slot][512] from gathered x
    gemm_tf32<<<dim3(MTILES, 4), 256, SMEM_DYN>>>(
        p_xr, p_gupr, p_hbuf, HD, ID, p_tok_idx, p_blk_e, (long)2*ID*HD, 1, 1);
    // expert down: dres[slot][1024]
    gemm_tf32<<<dim3(MTILES, 4), 256, SMEM_DYN>>>(
        p_hbuf, p_downr, p_dres, ID, HD, nullptr, p_blk_e, (long)HD*ID, 0, 1);
    // shared gate/up (fused silu): gbuf[token][2048]
    gemm_tf32<<<dim3(N/128, 16), 256, SMEM_DYN>>>(
        p_xr, p_sgur, p_gbuf, HD, ISD, nullptr, nullptr, 0, 1, 0);
    // shared down + fused final combine -> out
    gemm_tf32<<<dim3(N/128, 4), 256, SMEM_DYN>>>(
        p_gbuf, p_sdpr, out, ISD, HD, nullptr, nullptr, 0, 2, 0);
}

// round 9
// speedup vs baseline: 3.1299x; 1.7453x over previous
#include <cuda_runtime.h>
#include <cuda_fp16.h>
#include <cstdint>
#include <math.h>

// ---------------- problem constants ----------------
#define NE   16
#define HD   1024
#define ID   512
#define ISD  2048
#define NTOK 8192
#define SLOT_CAP (NTOK*2 + NE*128)   // 18432
#define MTILES   (SLOT_CAP/128)      // 144
#define STAGES   4
#define PH       40                   // smem row stride in halves (80B = 20 words)
#define A_HALVES (128*PH)             // 5120
#define B_HALVES (256*PH)             // 10240
#define STG_HALVES (A_HALVES + B_HALVES)   // 15360
#define STG_BYTES  (STG_HALVES*2)          // 30720
#define SMEM_DYN   (STAGES*STG_BYTES)      // 122880

// ---------------- scratch (device globals) ----------------
__device__ __half g_hbufh[(size_t)SLOT_CAP * ID];    // silu(g)*u per slot (fp16)
__device__ float  g_dres [(size_t)SLOT_CAP * HD];    // expert down output (fp32)
__device__ __half g_gbufh[(size_t)NTOK * ISD];       // shared silu(g)*u (fp16)
__device__ __half g_xh   [(size_t)NTOK * HD];        // x in fp16
__device__ __half g_guph [(size_t)NE * 2 * ID * HD]; // interleaved g/u expert weights (fp16)
__device__ __half g_downh[(size_t)NE * HD * ID];     // fp16
__device__ __half g_sguh [(size_t)2 * ISD * HD];     // interleaved shared g/u weights (fp16)
__device__ __half g_sdph [(size_t)HD * ISD];         // fp16
__device__ int   g_tok_idx[SLOT_CAP];
__device__ int   g_slot_of[NTOK*2];
__device__ int   g_sel[NTOK*2];
__device__ float g_w[NTOK*2];
__device__ float g_sgate[NTOK];
__device__ int   g_cnt[NE];
__device__ float g_probsum[NE];
__device__ int   g_fill[NE];
__device__ int   g_eoff[NE+1];
__device__ int   g_blk_e[MTILES];
__device__ int   g_total;

// ---------------- K0: init ----------------
__global__ void init_kernel() {
    int i = blockIdx.x * blockDim.x + threadIdx.x;
    if (i < SLOT_CAP) g_tok_idx[i] = -1;
    if (i < NE) { g_cnt[i] = 0; g_probsum[i] = 0.f; g_fill[i] = 0; }
}

// ---------------- K1: router (one warp per token, fp32 exact) ----------------
__global__ void router_kernel(const float* __restrict__ x,
                              const float* __restrict__ gw,
                              const float* __restrict__ segw, int N) {
    int warp = (blockIdx.x * blockDim.x + threadIdx.x) >> 5;
    int lane = threadIdx.x & 31;
    __shared__ float s_ps[NE];
    __shared__ int   s_cnt[NE];
    if (threadIdx.x < NE) { s_ps[threadIdx.x] = 0.f; s_cnt[threadIdx.x] = 0; }
    __syncthreads();

    if (warp < N) {
        float acc[17];
        #pragma unroll
        for (int j = 0; j < 17; j++) acc[j] = 0.f;
        const float* xr = x + (size_t)warp * HD;
        for (int k = lane; k < HD; k += 32) {
            float xv = __ldg(xr + k);
            #pragma unroll
            for (int j = 0; j < NE; j++) acc[j] += xv * __ldg(gw + j * HD + k);
            acc[16] += xv * __ldg(segw + k);
        }
        #pragma unroll
        for (int j = 0; j < 17; j++) {
            #pragma unroll
            for (int o = 16; o > 0; o >>= 1)
                acc[j] += __shfl_xor_sync(0xffffffffu, acc[j], o);
        }
        float mx = acc[0];
        #pragma unroll
        for (int j = 1; j < NE; j++) mx = fmaxf(mx, acc[j]);
        float p[NE]; float s = 0.f;
        #pragma unroll
        for (int j = 0; j < NE; j++) { p[j] = expf(acc[j] - mx); s += p[j]; }
        float inv = 1.f / s;
        #pragma unroll
        for (int j = 0; j < NE; j++) p[j] *= inv;
        int a0 = 0;
        #pragma unroll
        for (int j = 1; j < NE; j++) if (p[j] > p[a0]) a0 = j;
        int a1 = (a0 == 0) ? 1 : 0;
        #pragma unroll
        for (int j = 0; j < NE; j++) if (j != a0 && p[j] > p[a1]) a1 = j;
        float ww = p[a0] + p[a1];
        if (lane == 0) {
            g_sel[warp*2]   = a0;  g_sel[warp*2+1] = a1;
            g_w[warp*2]     = p[a0] / ww;
            g_w[warp*2+1]   = p[a1] / ww;
            g_sgate[warp]   = 1.f / (1.f + expf(-acc[16]));
            atomicAdd(&s_cnt[a0], 1); atomicAdd(&s_cnt[a1], 1);
        }
        if (lane < NE) atomicAdd(&s_ps[lane], p[lane]);
    }
    __syncthreads();
    if (threadIdx.x < NE) {
        atomicAdd(&g_probsum[threadIdx.x], s_ps[threadIdx.x]);
        atomicAdd(&g_cnt[threadIdx.x], s_cnt[threadIdx.x]);
    }
}

// ---------------- K2: offsets + aux loss ----------------
__global__ void offsets_kernel(float* __restrict__ out, long aux_index, int N) {
    if (threadIdx.x == 0 && blockIdx.x == 0) {
        int off = 0;
        for (int e = 0; e < NE; e++) {
            g_eoff[e] = off;
            off += ((g_cnt[e] + 127) / 128) * 128;
        }
        g_eoff[NE] = off;
        g_total = off;
        for (int e = 0; e < NE; e++)
            for (int t = g_eoff[e] / 128; t < g_eoff[e+1] / 128; t++)
                g_blk_e[t] = e;
        float aux = 0.f;
        for (int e = 0; e < NE; e++)
            aux += ((float)g_cnt[e] / (float)(N * 2)) * (g_probsum[e] / (float)N);
        out[aux_index] = (float)NE * aux;
    }
}

// ---------------- K3: slot assignment ----------------
__global__ void assign_kernel(int N) {
    int t = blockIdx.x * blockDim.x + threadIdx.x;
    if (t < N) {
        #pragma unroll
        for (int i = 0; i < 2; i++) {
            int e = g_sel[t*2 + i];
            int pos = atomicAdd(&g_fill[e], 1);
            int slot = g_eoff[e] + pos;
            g_tok_idx[slot] = t;
            g_slot_of[t*2 + i] = slot;
        }
    }
}

// ---------------- conversion kernels (fp32 -> fp16 RN) ----------------
__global__ void tohalf4(const float4* __restrict__ src, __half* __restrict__ dst, long n4) {
    long i = blockIdx.x * (long)blockDim.x + threadIdx.x;
    if (i < n4) {
        float4 v = src[i];
        __half2 h0 = __floats2half2_rn(v.x, v.y);
        __half2 h1 = __floats2half2_rn(v.z, v.w);
        uint2 pk = make_uint2(*(unsigned*)&h0, *(unsigned*)&h1);
        *(uint2*)(dst + i * 4) = pk;
    }
}

// gup [E][2I][H] -> interleaved fp16: dst row 2j = gate_j, 2j+1 = up_j (per expert)
__global__ void interleave_gup_kernel(const float* __restrict__ src, __half* __restrict__ dst) {
    long i4 = blockIdx.x * (long)blockDim.x + threadIdx.x;
    long total4 = (long)NE * 2 * ID * HD / 4;
    if (i4 >= total4) return;
    long i = i4 * 4;
    long e = i >> 20;
    int  r = (int)((i >> 10) & 1023);
    int  k = (int)(i & 1023);
    int  j = r >> 1;
    int  sr = (r & 1) ? (ID + j) : j;
    float4 v = *(const float4*)(src + (e << 20) + (size_t)sr * HD + k);
    __half2 h0 = __floats2half2_rn(v.x, v.y);
    __half2 h1 = __floats2half2_rn(v.z, v.w);
    *(uint2*)(dst + i) = make_uint2(*(unsigned*)&h0, *(unsigned*)&h1);
}

// sgp/sup [IS][H] -> interleaved fp16 [2*IS][H]
__global__ void interleave_sgu_kernel(const float* __restrict__ g, const float* __restrict__ u,
                                      __half* __restrict__ dst) {
    long i4 = blockIdx.x * (long)blockDim.x + threadIdx.x;
    long total4 = (long)2 * ISD * HD / 4;
    if (i4 >= total4) return;
    long i = i4 * 4;
    int r = (int)(i >> 10);
    int k = (int)(i & 1023);
    int j = r >> 1;
    const float* s = (r & 1) ? u : g;
    float4 v = *(const float4*)(s + (size_t)j * HD + k);
    __half2 h0 = __floats2half2_rn(v.x, v.y);
    __half2 h1 = __floats2half2_rn(v.z, v.w);
    *(uint2*)(dst + i) = make_uint2(*(unsigned*)&h0, *(unsigned*)&h1);
}

// ---------------- fp16 mma.sync GEMM: C[M,N] = A[M,K] @ B[N,K]^T ----------------
// CTA tile 128x256, warp tile 64x64, ktile K=32 halves (2x m16n8k16 per frag set).
// 4-stage 16B-cp.async pipeline, row-major smem [row][32] stride PH=40 halves
// (conflict-free 16B stores and half2 fragment LDS).
// row_map: optional gather for A rows (-1 => zero row).
// blk_e:   per-m-tile expert selection for B (+ e*estride).
// mode: 0 = plain f32 store; 1 = fused silu on interleaved (g,u) cols -> half C[.][col/2];
//       2 = fused final combine: f32 C = c*sgate + w0*dres[s0] + w1*dres[s1].
__global__ __launch_bounds__(256, 1)
void gemm_f16(const __half* __restrict__ A, const __half* __restrict__ B,
              void* __restrict__ Cv, int K, int ldc,
              const int* __restrict__ row_map,
              const int* __restrict__ blk_e, long estride,
              int mode, int m_from_dev)
{
    const int M = m_from_dev ? g_total : (int)(gridDim.x * 128);
    const int m0 = blockIdx.x * 128;
    if (m0 >= M) return;
    const int n0 = blockIdx.y * 256;

    extern __shared__ __half dsm[];
    const uint32_t sbase = (uint32_t)__cvta_generic_to_shared(dsm);

    const int t    = threadIdx.x;
    const int lane = t & 31;
    const int wid  = t >> 5;
    const int wm0  = (wid & 1) * 64;
    const int wn0  = (wid >> 1) * 64;
    const int tg   = lane & 3;
    const int gid  = lane >> 2;

    // fetch mapping: thread owns A row (t&127), B rows (t&127, +128);
    // within each row, 16 consecutive halves at offset (t>>7)*16, as 2x16B chunks.
    const int frow = t & 127;
    const int h0   = (t >> 7) * 16;     // half offset within ktile row
    const __half* aptr;
    unsigned asz;
    if (row_map) {
        int tok = __ldg(&row_map[m0 + frow]);
        asz  = (tok < 0) ? 0u : 16u;
        aptr = A + (size_t)(tok < 0 ? 0 : tok) * K;
    } else {
        asz  = 16u;
        aptr = A + (size_t)(m0 + frow) * K;
    }
    const __half* Bp = blk_e ? (B + (size_t)__ldg(&blk_e[blockIdx.x]) * estride) : B;
    const __half* bptr0 = Bp + (size_t)(n0 + frow) * K;
    const __half* bptr1 = Bp + (size_t)(n0 + frow + 128) * K;

    const uint32_t aDst  = sbase + (uint32_t)(frow * PH + h0) * 2u;
    const uint32_t bDst0 = sbase + (uint32_t)(A_HALVES + frow * PH + h0) * 2u;
    const uint32_t bDst1 = sbase + (uint32_t)(A_HALVES + (frow + 128) * PH + h0) * 2u;

    const int KT = K >> 5;              // ktile = 32 halves

    float c[4][8][4];
    #pragma unroll
    for (int mi = 0; mi < 4; mi++)
        #pragma unroll
        for (int ni = 0; ni < 8; ni++)
            #pragma unroll
            for (int q = 0; q < 4; q++) c[mi][ni][q] = 0.f;

    auto fetch = [&](int kt_f) {
        uint32_t st = (uint32_t)(kt_f & (STAGES - 1)) * STG_BYTES;
        unsigned koff = (unsigned)(kt_f * 32 + h0);
        asm volatile("cp.async.cg.shared.global [%0], [%1], 16, %2;"
                     :: "r"(aDst + st), "l"(aptr + koff), "r"(asz));
        asm volatile("cp.async.cg.shared.global [%0], [%1], 16, %2;"
                     :: "r"(aDst + st + 16), "l"(aptr + koff + 8), "r"(asz));
        asm volatile("cp.async.cg.shared.global [%0], [%1], 16, 16;"
                     :: "r"(bDst0 + st), "l"(bptr0 + koff));
        asm volatile("cp.async.cg.shared.global [%0], [%1], 16, 16;"
                     :: "r"(bDst0 + st + 16), "l"(bptr0 + koff + 8));
        asm volatile("cp.async.cg.shared.global [%0], [%1], 16, 16;"
                     :: "r"(bDst1 + st), "l"(bptr1 + koff));
        asm volatile("cp.async.cg.shared.global [%0], [%1], 16, 16;"
                     :: "r"(bDst1 + st + 16), "l"(bptr1 + koff + 8));
    };

    #pragma unroll
    for (int s = 0; s < STAGES - 1; s++) {
        fetch(s);                       // KT >= 16 always
        asm volatile("cp.async.commit_group;");
    }

    for (int kt = 0; kt < KT; kt++) {
        asm volatile("cp.async.wait_group %0;" :: "n"(STAGES - 2));
        __syncthreads();
        int ft = kt + STAGES - 1;
        if (ft < KT) fetch(ft);
        asm volatile("cp.async.commit_group;");

        const __half* Sa = dsm + (kt & (STAGES - 1)) * STG_HALVES;
        const __half* Sb = Sa + A_HALVES;
        #pragma unroll
        for (int ks = 0; ks < 2; ks++) {
            const int kk = ks * 16;                // half offset
            unsigned a[4][4], b[8][2];
            #pragma unroll
            for (int mi = 0; mi < 4; mi++) {
                int m = wm0 + mi * 16 + gid;
                a[mi][0] = *(const unsigned*)&Sa[m * PH + kk + 2 * tg];
                a[mi][1] = *(const unsigned*)&Sa[(m + 8) * PH + kk + 2 * tg];
                a[mi][2] = *(const unsigned*)&Sa[m * PH + kk + 8 + 2 * tg];
                a[mi][3] = *(const unsigned*)&Sa[(m + 8) * PH + kk + 8 + 2 * tg];
            }
            #pragma unroll
            for (int ni = 0; ni < 8; ni++) {
                int n = wn0 + ni * 8 + gid;
                b[ni][0] = *(const unsigned*)&Sb[n * PH + kk + 2 * tg];
                b[ni][1] = *(const unsigned*)&Sb[n * PH + kk + 8 + 2 * tg];
            }
            #pragma unroll
            for (int mi = 0; mi < 4; mi++)
                #pragma unroll
                for (int ni = 0; ni < 8; ni++)
                    asm volatile(
                        "mma.sync.aligned.m16n8k16.row.col.f32.f16.f16.f32 "
                        "{%0,%1,%2,%3}, {%4,%5,%6,%7}, {%8,%9}, {%0,%1,%2,%3};\n"
                        : "+f"(c[mi][ni][0]), "+f"(c[mi][ni][1]),
                          "+f"(c[mi][ni][2]), "+f"(c[mi][ni][3])
                        : "r"(a[mi][0]), "r"(a[mi][1]), "r"(a[mi][2]), "r"(a[mi][3]),
                          "r"(b[ni][0]), "r"(b[ni][1]));
        }
    }

    // ---------------- epilogue ----------------
    const int tg2 = tg * 2;
    if (mode == 1) {                      // fused silu -> half output at col/2
        __half* Ch = (__half*)Cv;
        #pragma unroll
        for (int mi = 0; mi < 4; mi++) {
            int r = m0 + wm0 + mi * 16 + gid;
            #pragma unroll
            for (int ni = 0; ni < 8; ni++) {
                int cc = (n0 + wn0 + ni * 8 + tg2) >> 1;
                float g0 = c[mi][ni][0], u0 = c[mi][ni][1];
                float g1 = c[mi][ni][2], u1 = c[mi][ni][3];
                float hv0 = (g0 / (1.f + __expf(-g0))) * u0;
                float hv1 = (g1 / (1.f + __expf(-g1))) * u1;
                Ch[(size_t)r * ldc + cc]       = __float2half_rn(hv0);
                Ch[(size_t)(r + 8) * ldc + cc] = __float2half_rn(hv1);
            }
        }
    } else if (mode == 2) {               // fused final combine -> f32 out
        float* Cf = (float*)Cv;
        #pragma unroll
        for (int mi = 0; mi < 4; mi++) {
            int r0 = m0 + wm0 + mi * 16 + gid;
            int r1 = r0 + 8;
            float w00 = g_w[2*r0], w01 = g_w[2*r0+1], sg0 = g_sgate[r0];
            int   s00 = g_slot_of[2*r0], s01 = g_slot_of[2*r0+1];
            float w10 = g_w[2*r1], w11 = g_w[2*r1+1], sg1 = g_sgate[r1];
            int   s10 = g_slot_of[2*r1], s11 = g_slot_of[2*r1+1];
            #pragma unroll
            for (int ni = 0; ni < 8; ni++) {
                int cc = n0 + wn0 + ni * 8 + tg2;
                float2 d00 = *(const float2*)&g_dres[(size_t)s00 * HD + cc];
                float2 d01 = *(const float2*)&g_dres[(size_t)s01 * HD + cc];
                float2 o0;
                o0.x = c[mi][ni][0] * sg0 + w00 * d00.x + w01 * d01.x;
                o0.y = c[mi][ni][1] * sg0 + w00 * d00.y + w01 * d01.y;
                *(float2*)(Cf + (size_t)r0 * ldc + cc) = o0;
                float2 d10 = *(const float2*)&g_dres[(size_t)s10 * HD + cc];
                float2 d11 = *(const float2*)&g_dres[(size_t)s11 * HD + cc];
                float2 o1;
                o1.x = c[mi][ni][2] * sg1 + w10 * d10.x + w11 * d11.x;
                o1.y = c[mi][ni][3] * sg1 + w10 * d10.y + w11 * d11.y;
                *(float2*)(Cf + (size_t)r1 * ldc + cc) = o1;
            }
        }
    } else {                              // plain f32
        float* Cf = (float*)Cv;
        #pragma unroll
        for (int mi = 0; mi < 4; mi++) {
            #pragma unroll
            for (int ni = 0; ni < 8; ni++) {
                int r  = m0 + wm0 + mi * 16 + gid;
                int cc = n0 + wn0 + ni * 8 + tg2;
                *(float2*)(Cf + (size_t)r * ldc + cc)       = make_float2(c[mi][ni][0], c[mi][ni][1]);
                *(float2*)(Cf + (size_t)(r + 8) * ldc + cc) = make_float2(c[mi][ni][2], c[mi][ni][3]);
            }
        }
    }
}

// ---------------- launch ----------------
extern "C" void kernel_launch(void* const* d_in, const int* in_sizes, int n_in,
                              void* d_out, int out_size) {
    const float* x    = (const float*)d_in[0];
    const float* gw   = (const float*)d_in[1];
    const float* gup  = (const float*)d_in[2];
    const float* down = (const float*)d_in[3];
    const float* sgp  = (const float*)d_in[4];
    const float* sup  = (const float*)d_in[5];
    const float* sdp  = (const float*)d_in[6];
    const float* segw = (const float*)d_in[7];
    float* out = (float*)d_out;
    int N = in_sizes[0] / HD;   // 8192

    __half *p_hbuf, *p_gbuf, *p_xh, *p_guph, *p_downh, *p_sguh, *p_sdph;
    float *p_dres;
    int *p_tok_idx, *p_blk_e;
    cudaGetSymbolAddress((void**)&p_hbuf,   g_hbufh);
    cudaGetSymbolAddress((void**)&p_dres,   g_dres);
    cudaGetSymbolAddress((void**)&p_gbuf,   g_gbufh);
    cudaGetSymbolAddress((void**)&p_xh,     g_xh);
    cudaGetSymbolAddress((void**)&p_guph,   g_guph);
    cudaGetSymbolAddress((void**)&p_downh,  g_downh);
    cudaGetSymbolAddress((void**)&p_sguh,   g_sguh);
    cudaGetSymbolAddress((void**)&p_sdph,   g_sdph);
    cudaGetSymbolAddress((void**)&p_tok_idx, g_tok_idx);
    cudaGetSymbolAddress((void**)&p_blk_e,  g_blk_e);

    cudaFuncSetAttribute(gemm_f16, cudaFuncAttributeMaxDynamicSharedMemorySize, SMEM_DYN);

    init_kernel<<<(SLOT_CAP + 255) / 256, 256>>>();
    router_kernel<<<(N + 7) / 8, 256>>>(x, gw, segw, N);
    offsets_kernel<<<1, 32>>>(out, (long)out_size - 1, N);
    assign_kernel<<<(N + 255) / 256, 256>>>(N);

    // conversions to fp16 (g/u row interleaving for fused silu)
    interleave_gup_kernel<<<(int)((long)NE*2*ID*HD/4/256), 256>>>(gup, p_guph);
    tohalf4<<<(int)((long)NE*HD*ID/4/256), 256>>>((const float4*)down, p_downh, (long)NE*HD*ID/4);
    interleave_sgu_kernel<<<(int)((long)2*ISD*HD/4/256), 256>>>(sgp, sup, p_sguh);
    tohalf4<<<(int)((long)HD*ISD/4/256), 256>>>((const float4*)sdp, p_sdph, (long)HD*ISD/4);
    tohalf4<<<(int)((long)N*HD/4/256), 256>>>((const float4*)x, p_xh, (long)N*HD/4);

    // expert gate_up (fused silu): hbuf[slot][512] (fp16) from gathered x
    gemm_f16<<<dim3(MTILES, 4), 256, SMEM_DYN>>>(
        p_xh, p_guph, p_hbuf, HD, ID, p_tok_idx, p_blk_e, (long)2*ID*HD, 1, 1);
    // expert down: dres[slot][1024] (f32)
    gemm_f16<<<dim3(MTILES, 4), 256, SMEM_DYN>>>(
        p_hbuf, p_downh, p_dres, ID, HD, nullptr, p_blk_e, (long)HD*ID, 0, 1);
    // shared gate/up (fused silu): gbuf[token][2048] (fp16)
    gemm_f16<<<dim3(N/128, 16), 256, SMEM_DYN>>>(
        p_xh, p_sguh, p_gbuf, HD, ISD, nullptr, nullptr, 0, 1, 0);
    // shared down + fused final combine -> out (f32)
    gemm_f16<<<dim3(N/128, 4), 256, SMEM_DYN>>>(
        p_gbuf, p_sdph, out, ISD, HD, nullptr, nullptr, 0, 2, 0);
}

// round 11
// speedup vs baseline: 3.2078x; 1.0249x over previous
#include <cuda_runtime.h>
#include <cuda_fp16.h>
#include <cstdint>
#include <math.h>

// ---------------- problem constants ----------------
#define NE   16
#define HD   1024
#define ID   512
#define ISD  2048
#define NTOK 8192
#define SLOT_CAP (NTOK*2 + NE*128)   // 18432
#define MTILES   (SLOT_CAP/128)      // 144
#define STAGES   3
#define PH2      72                   // smem row stride in halves (144B)
#define A_H      (128*PH2)            // 9216 halves
#define B_H      (256*PH2)            // 18432 halves
#define STG_H    (A_H + B_H)          // 27648
#define STG_BYTES (STG_H*2)           // 55296
#define SMEM_DYN (STAGES*STG_BYTES)   // 165888

// ---------------- scratch (device globals) ----------------
__device__ __half g_hbufh[(size_t)SLOT_CAP * ID];    // silu(g)*u per slot (fp16)
__device__ float  g_dres [(size_t)SLOT_CAP * HD];    // expert down output (fp32)
__device__ __half g_gbufh[(size_t)NTOK * ISD];       // shared silu(g)*u (fp16)
__device__ __half g_xh   [(size_t)NTOK * HD];        // x in fp16
__device__ __half g_guph [(size_t)NE * 2 * ID * HD]; // interleaved g/u expert weights (fp16)
__device__ __half g_downh[(size_t)NE * HD * ID];     // fp16
__device__ __half g_sguh [(size_t)2 * ISD * HD];     // interleaved shared g/u weights (fp16)
__device__ __half g_sdph [(size_t)HD * ISD];         // fp16
__device__ int   g_tok_idx[SLOT_CAP];
__device__ int   g_slot_of[NTOK*2];
__device__ int   g_sel[NTOK*2];
__device__ float g_w[NTOK*2];
__device__ float g_sgate[NTOK];
__device__ int   g_cnt[NE];
__device__ float g_probsum[NE];
__device__ int   g_fill[NE];
__device__ int   g_eoff[NE+1];
__device__ int   g_blk_e[MTILES];
__device__ int   g_total;

// ---------------- K0: init ----------------
__global__ void init_kernel() {
    int i = blockIdx.x * blockDim.x + threadIdx.x;
    if (i < SLOT_CAP) g_tok_idx[i] = -1;
    if (i < NE) { g_cnt[i] = 0; g_probsum[i] = 0.f; g_fill[i] = 0; }
}

// ---------------- K1: router (one warp per token, fp32 exact) ----------------
__global__ void router_kernel(const float* __restrict__ x,
                              const float* __restrict__ gw,
                              const float* __restrict__ segw, int N) {
    int warp = (blockIdx.x * blockDim.x + threadIdx.x) >> 5;
    int lane = threadIdx.x & 31;
    __shared__ float s_ps[NE];
    __shared__ int   s_cnt[NE];
    if (threadIdx.x < NE) { s_ps[threadIdx.x] = 0.f; s_cnt[threadIdx.x] = 0; }
    __syncthreads();

    if (warp < N) {
        float acc[17];
        #pragma unroll
        for (int j = 0; j < 17; j++) acc[j] = 0.f;
        const float* xr = x + (size_t)warp * HD;
        for (int k = lane; k < HD; k += 32) {
            float xv = __ldg(xr + k);
            #pragma unroll
            for (int j = 0; j < NE; j++) acc[j] += xv * __ldg(gw + j * HD + k);
            acc[16] += xv * __ldg(segw + k);
        }
        #pragma unroll
        for (int j = 0; j < 17; j++) {
            #pragma unroll
            for (int o = 16; o > 0; o >>= 1)
                acc[j] += __shfl_xor_sync(0xffffffffu, acc[j], o);
        }
        float mx = acc[0];
        #pragma unroll
        for (int j = 1; j < NE; j++) mx = fmaxf(mx, acc[j]);
        float p[NE]; float s = 0.f;
        #pragma unroll
        for (int j = 0; j < NE; j++) { p[j] = expf(acc[j] - mx); s += p[j]; }
        float inv = 1.f / s;
        #pragma unroll
        for (int j = 0; j < NE; j++) p[j] *= inv;
        int a0 = 0;
        #pragma unroll
        for (int j = 1; j < NE; j++) if (p[j] > p[a0]) a0 = j;
        int a1 = (a0 == 0) ? 1 : 0;
        #pragma unroll
        for (int j = 0; j < NE; j++) if (j != a0 && p[j] > p[a1]) a1 = j;
        float ww = p[a0] + p[a1];
        if (lane == 0) {
            g_sel[warp*2]   = a0;  g_sel[warp*2+1] = a1;
            g_w[warp*2]     = p[a0] / ww;
            g_w[warp*2+1]   = p[a1] / ww;
            g_sgate[warp]   = 1.f / (1.f + expf(-acc[16]));
            atomicAdd(&s_cnt[a0], 1); atomicAdd(&s_cnt[a1], 1);
        }
        if (lane < NE) atomicAdd(&s_ps[lane], p[lane]);
    }
    __syncthreads();
    if (threadIdx.x < NE) {
        atomicAdd(&g_probsum[threadIdx.x], s_ps[threadIdx.x]);
        atomicAdd(&g_cnt[threadIdx.x], s_cnt[threadIdx.x]);
    }
}

// ---------------- K2: offsets + aux loss ----------------
__global__ void offsets_kernel(float* __restrict__ out, long aux_index, int N) {
    if (threadIdx.x == 0 && blockIdx.x == 0) {
        int off = 0;
        for (int e = 0; e < NE; e++) {
            g_eoff[e] = off;
            off += ((g_cnt[e] + 127) / 128) * 128;
        }
        g_eoff[NE] = off;
        g_total = off;
        for (int e = 0; e < NE; e++)
            for (int t = g_eoff[e] / 128; t < g_eoff[e+1] / 128; t++)
                g_blk_e[t] = e;
        float aux = 0.f;
        for (int e = 0; e < NE; e++)
            aux += ((float)g_cnt[e] / (float)(N * 2)) * (g_probsum[e] / (float)N);
        out[aux_index] = (float)NE * aux;
    }
}

// ---------------- K3: slot assignment ----------------
__global__ void assign_kernel(int N) {
    int t = blockIdx.x * blockDim.x + threadIdx.x;
    if (t < N) {
        #pragma unroll
        for (int i = 0; i < 2; i++) {
            int e = g_sel[t*2 + i];
            int pos = atomicAdd(&g_fill[e], 1);
            int slot = g_eoff[e] + pos;
            g_tok_idx[slot] = t;
            g_slot_of[t*2 + i] = slot;
        }
    }
}

// ---------------- conversion kernels (fp32 -> fp16 RN) ----------------
__global__ void tohalf4(const float4* __restrict__ src, __half* __restrict__ dst, long n4) {
    long i = blockIdx.x * (long)blockDim.x + threadIdx.x;
    if (i < n4) {
        float4 v = src[i];
        __half2 h0 = __floats2half2_rn(v.x, v.y);
        __half2 h1 = __floats2half2_rn(v.z, v.w);
        *(uint2*)(dst + i * 4) = make_uint2(*(unsigned*)&h0, *(unsigned*)&h1);
    }
}

// gup [E][2I][H] -> interleaved fp16: dst row 2j = gate_j, 2j+1 = up_j (per expert)
__global__ void interleave_gup_kernel(const float* __restrict__ src, __half* __restrict__ dst) {
    long i4 = blockIdx.x * (long)blockDim.x + threadIdx.x;
    long total4 = (long)NE * 2 * ID * HD / 4;
    if (i4 >= total4) return;
    long i = i4 * 4;
    long e = i >> 20;
    int  r = (int)((i >> 10) & 1023);
    int  k = (int)(i & 1023);
    int  j = r >> 1;
    int  sr = (r & 1) ? (ID + j) : j;
    float4 v = *(const float4*)(src + (e << 20) + (size_t)sr * HD + k);
    __half2 h0 = __floats2half2_rn(v.x, v.y);
    __half2 h1 = __floats2half2_rn(v.z, v.w);
    *(uint2*)(dst + i) = make_uint2(*(unsigned*)&h0, *(unsigned*)&h1);
}

// sgp/sup [IS][H] -> interleaved fp16 [2*IS][H]
__global__ void interleave_sgu_kernel(const float* __restrict__ g, const float* __restrict__ u,
                                      __half* __restrict__ dst) {
    long i4 = blockIdx.x * (long)blockDim.x + threadIdx.x;
    long total4 = (long)2 * ISD * HD / 4;
    if (i4 >= total4) return;
    long i = i4 * 4;
    int r = (int)(i >> 10);
    int k = (int)(i & 1023);
    int j = r >> 1;
    const float* s = (r & 1) ? u : g;
    float4 v = *(const float4*)(s + (size_t)j * HD + k);
    __half2 h0 = __floats2half2_rn(v.x, v.y);
    __half2 h1 = __floats2half2_rn(v.z, v.w);
    *(uint2*)(dst + i) = make_uint2(*(unsigned*)&h0, *(unsigned*)&h1);
}

// ---------------- fp16 mma.sync GEMM: C[M,N] = A[M,K] @ B[N,K]^T ----------------
// CTA tile 128x256, warp tile 64x64. ktile K=64 halves (4 x k16 substeps).
// 3-stage 16B-cp.async pipeline, row-major smem [row][64] stride PH2=72 halves
// (conflict-free 16B stores, conflict-free ldmatrix). ldmatrix x4 (non-trans for
// both A and B: B stored [n][k] row-major delivers the col fragment directly).
// row_map: optional gather for A rows (-1 => zero row).
// blk_e:   per-m-tile expert selection for B (+ e*estride).
// mode: 0 = plain f32 store; 1 = fused silu on interleaved (g,u) cols -> half C[.][col/2];
//       2 = fused final combine: f32 C = c*sgate + w0*dres[s0] + w1*dres[s1].
__global__ __launch_bounds__(256, 1)
void gemm_f16(const __half* __restrict__ A, const __half* __restrict__ B,
              void* __restrict__ Cv, int K, int ldc,
              const int* __restrict__ row_map,
              const int* __restrict__ blk_e, long estride,
              int mode, int m_from_dev)
{
    const int M = m_from_dev ? g_total : (int)(gridDim.x * 128);
    const int m0 = blockIdx.x * 128;
    if (m0 >= M) return;
    const int n0 = blockIdx.y * 256;

    extern __shared__ __half dsm[];
    const uint32_t sbase = (uint32_t)__cvta_generic_to_shared(dsm);

    const int t    = threadIdx.x;
    const int lane = t & 31;
    const int wid  = t >> 5;
    const int wm0  = (wid & 1) * 64;
    const int wn0  = (wid >> 1) * 64;
    const int tg   = lane & 3;
    const int gid  = lane >> 2;

    // fetch mapping: row frow, halves [h0, h0+32) as 4x16B chunks
    const int frow = t & 127;
    const int h0   = (t >> 7) * 32;
    const __half* aptr;
    unsigned asz;
    if (row_map) {
        int tok = __ldg(&row_map[m0 + frow]);
        asz  = (tok < 0) ? 0u : 16u;
        aptr = A + (size_t)(tok < 0 ? 0 : tok) * K;
    } else {
        asz  = 16u;
        aptr = A + (size_t)(m0 + frow) * K;
    }
    const __half* Bp = blk_e ? (B + (size_t)__ldg(&blk_e[blockIdx.x]) * estride) : B;
    const __half* bptr0 = Bp + (size_t)(n0 + frow) * K;
    const __half* bptr1 = Bp + (size_t)(n0 + frow + 128) * K;

    const uint32_t aDst  = sbase + (uint32_t)(frow * PH2 + h0) * 2u;
    const uint32_t bDst0 = sbase + (uint32_t)(A_H + frow * PH2 + h0) * 2u;
    const uint32_t bDst1 = sbase + (uint32_t)(A_H + (frow + 128) * PH2 + h0) * 2u;

    const int KT = K >> 6;             // ktile = 64 halves

    // ldmatrix lane address bases (stage-0; add stage offset + ks*32B in loop)
    const int alr = lane & 15;              // A row 0-15
    const int alc = (lane >> 4) * 8;        // A col 0/8
    uint32_t aLdBase[4];
    #pragma unroll
    for (int mi = 0; mi < 4; mi++)
        aLdBase[mi] = sbase + (uint32_t)((wm0 + mi * 16 + alr) * PH2 + alc) * 2u;
    // B tiles per x4: t0=(n0-7,k0-7)->b[2nj][0], t1=(n0-7,k8-15)->b[2nj][1],
    //                 t2=(n8-15,k0-7)->b[2nj+1][0], t3=(n8-15,k8-15)->b[2nj+1][1]
    const int blr = (lane & 7) + ((lane >> 4) * 8);   // row within 16-n group
    const int blc = ((lane >> 3) & 1) * 8;            // col 0/8
    uint32_t bLdBase[4];
    #pragma unroll
    for (int nj = 0; nj < 4; nj++)
        bLdBase[nj] = sbase + (uint32_t)(A_H + (wn0 + nj * 16 + blr) * PH2 + blc) * 2u;

    float c[4][8][4];
    #pragma unroll
    for (int mi = 0; mi < 4; mi++)
        #pragma unroll
        for (int ni = 0; ni < 8; ni++)
            #pragma unroll
            for (int q = 0; q < 4; q++) c[mi][ni][q] = 0.f;

    auto fetch = [&](int kt_f, int slot) {
        uint32_t st = (uint32_t)slot * STG_BYTES;
        unsigned koff = (unsigned)(kt_f * 64 + h0);
        #pragma unroll
        for (int cch = 0; cch < 4; cch++) {
            asm volatile("cp.async.cg.shared.global [%0], [%1], 16, %2;"
                         :: "r"(aDst + st + cch * 16), "l"(aptr + koff + cch * 8), "r"(asz));
            asm volatile("cp.async.cg.shared.global [%0], [%1], 16, 16;"
                         :: "r"(bDst0 + st + cch * 16), "l"(bptr0 + koff + cch * 8));
            asm volatile("cp.async.cg.shared.global [%0], [%1], 16, 16;"
                         :: "r"(bDst1 + st + cch * 16), "l"(bptr1 + koff + cch * 8));
        }
    };

    fetch(0, 0);
    asm volatile("cp.async.commit_group;");
    fetch(1, 1);
    asm volatile("cp.async.commit_group;");

    int cslot = 0, fslot = 2;
    for (int kt = 0; kt < KT; kt++) {
        asm volatile("cp.async.wait_group %0;" :: "n"(STAGES - 2));
        __syncthreads();
        int ft = kt + STAGES - 1;
        if (ft < KT) fetch(ft, fslot);
        asm volatile("cp.async.commit_group;");
        if (++fslot == STAGES) fslot = 0;

        const uint32_t stoff = (uint32_t)cslot * STG_BYTES;
        #pragma unroll
        for (int ks = 0; ks < 4; ks++) {
            const uint32_t kb = stoff + (uint32_t)ks * 32u;
            unsigned a[4][4], b[8][2];
            #pragma unroll
            for (int mi = 0; mi < 4; mi++)
                asm volatile("ldmatrix.sync.aligned.m8n8.x4.shared.b16 {%0,%1,%2,%3}, [%4];"
                             : "=r"(a[mi][0]), "=r"(a[mi][1]), "=r"(a[mi][2]), "=r"(a[mi][3])
                             : "r"(aLdBase[mi] + kb));
            #pragma unroll
            for (int nj = 0; nj < 4; nj++)
                asm volatile("ldmatrix.sync.aligned.m8n8.x4.shared.b16 {%0,%1,%2,%3}, [%4];"
                             : "=r"(b[2*nj][0]), "=r"(b[2*nj][1]),
                               "=r"(b[2*nj+1][0]), "=r"(b[2*nj+1][1])
                             : "r"(bLdBase[nj] + kb));
            #pragma unroll
            for (int mi = 0; mi < 4; mi++)
                #pragma unroll
                for (int ni = 0; ni < 8; ni++)
                    asm volatile(
                        "mma.sync.aligned.m16n8k16.row.col.f32.f16.f16.f32 "
                        "{%0,%1,%2,%3}, {%4,%5,%6,%7}, {%8,%9}, {%0,%1,%2,%3};\n"
                        : "+f"(c[mi][ni][0]), "+f"(c[mi][ni][1]),
                          "+f"(c[mi][ni][2]), "+f"(c[mi][ni][3])
                        : "r"(a[mi][0]), "r"(a[mi][1]), "r"(a[mi][2]), "r"(a[mi][3]),
                          "r"(b[ni][0]), "r"(b[ni][1]));
        }
        if (++cslot == STAGES) cslot = 0;
    }

    // ---------------- epilogue ----------------
    const int tg2 = tg * 2;
    if (mode == 1) {                      // fused silu -> half output at col/2
        __half* Ch = (__half*)Cv;
        #pragma unroll
        for (int mi = 0; mi < 4; mi++) {
            int r = m0 + wm0 + mi * 16 + gid;
            #pragma unroll
            for (int ni = 0; ni < 8; ni++) {
                int cc = (n0 + wn0 + ni * 8 + tg2) >> 1;
                float g0 = c[mi][ni][0], u0 = c[mi][ni][1];
                float g1 = c[mi][ni][2], u1 = c[mi][ni][3];
                float hv0 = (g0 / (1.f + __expf(-g0))) * u0;
                float hv1 = (g1 / (1.f + __expf(-g1))) * u1;
                Ch[(size_t)r * ldc + cc]       = __float2half_rn(hv0);
                Ch[(size_t)(r + 8) * ldc + cc] = __float2half_rn(hv1);
            }
        }
    } else if (mode == 2) {               // fused final combine -> f32 out
        float* Cf = (float*)Cv;
        #pragma unroll
        for (int mi = 0; mi < 4; mi++) {
            int r0 = m0 + wm0 + mi * 16 + gid;
            int r1 = r0 + 8;
            float w00 = g_w[2*r0], w01 = g_w[2*r0+1], sg0 = g_sgate[r0];
            int   s00 = g_slot_of[2*r0], s01 = g_slot_of[2*r0+1];
            float w10 = g_w[2*r1], w11 = g_w[2*r1+1], sg1 = g_sgate[r1];
            int   s10 = g_slot_of[2*r1], s11 = g_slot_of[2*r1+1];
            #pragma unroll
            for (int ni = 0; ni < 8; ni++) {
                int cc = n0 + wn0 + ni * 8 + tg2;
                float2 d00 = *(const float2*)&g_dres[(size_t)s00 * HD + cc];
                float2 d01 = *(const float2*)&g_dres[(size_t)s01 * HD + cc];
                float2 o0;
                o0.x = c[mi][ni][0] * sg0 + w00 * d00.x + w01 * d01.x;
                o0.y = c[mi][ni][1] * sg0 + w00 * d00.y + w01 * d01.y;
                *(float2*)(Cf + (size_t)r0 * ldc + cc) = o0;
                float2 d10 = *(const float2*)&g_dres[(size_t)s10 * HD + cc];
                float2 d11 = *(const float2*)&g_dres[(size_t)s11 * HD + cc];
                float2 o1;
                o1.x = c[mi][ni][2] * sg1 + w10 * d10.x + w11 * d11.x;
                o1.y = c[mi][ni][3] * sg1 + w10 * d10.y + w11 * d11.y;
                *(float2*)(Cf + (size_t)r1 * ldc + cc) = o1;
            }
        }
    } else {                              // plain f32
        float* Cf = (float*)Cv;
        #pragma unroll
        for (int mi = 0; mi < 4; mi++) {
            #pragma unroll
            for (int ni = 0; ni < 8; ni++) {
                int r  = m0 + wm0 + mi * 16 + gid;
                int cc = n0 + wn0 + ni * 8 + tg2;
                *(float2*)(Cf + (size_t)r * ldc + cc)       = make_float2(c[mi][ni][0], c[mi][ni][1]);
                *(float2*)(Cf + (size_t)(r + 8) * ldc + cc) = make_float2(c[mi][ni][2], c[mi][ni][3]);
            }
        }
    }
}

// ---------------- launch ----------------
extern "C" void kernel_launch(void* const* d_in, const int* in_sizes, int n_in,
                              void* d_out, int out_size) {
    const float* x    = (const float*)d_in[0];
    const float* gw   = (const float*)d_in[1];
    const float* gup  = (const float*)d_in[2];
    const float* down = (const float*)d_in[3];
    const float* sgp  = (const float*)d_in[4];
    const float* sup  = (const float*)d_in[5];
    const float* sdp  = (const float*)d_in[6];
    const float* segw = (const float*)d_in[7];
    float* out = (float*)d_out;
    int N = in_sizes[0] / HD;   // 8192

    __half *p_hbuf, *p_gbuf, *p_xh, *p_guph, *p_downh, *p_sguh, *p_sdph;
    float *p_dres;
    int *p_tok_idx, *p_blk_e;
    cudaGetSymbolAddress((void**)&p_hbuf,   g_hbufh);
    cudaGetSymbolAddress((void**)&p_dres,   g_dres);
    cudaGetSymbolAddress((void**)&p_gbuf,   g_gbufh);
    cudaGetSymbolAddress((void**)&p_xh,     g_xh);
    cudaGetSymbolAddress((void**)&p_guph,   g_guph);
    cudaGetSymbolAddress((void**)&p_downh,  g_downh);
    cudaGetSymbolAddress((void**)&p_sguh,   g_sguh);
    cudaGetSymbolAddress((void**)&p_sdph,   g_sdph);
    cudaGetSymbolAddress((void**)&p_tok_idx, g_tok_idx);
    cudaGetSymbolAddress((void**)&p_blk_e,  g_blk_e);

    cudaFuncSetAttribute(gemm_f16, cudaFuncAttributeMaxDynamicSharedMemorySize, SMEM_DYN);

    init_kernel<<<(SLOT_CAP + 255) / 256, 256>>>();
    router_kernel<<<(N + 7) / 8, 256>>>(x, gw, segw, N);
    offsets_kernel<<<1, 32>>>(out, (long)out_size - 1, N);
    assign_kernel<<<(N + 255) / 256, 256>>>(N);

    // conversions to fp16 (g/u row interleaving for fused silu)
    interleave_gup_kernel<<<(int)((long)NE*2*ID*HD/4/256), 256>>>(gup, p_guph);
    tohalf4<<<(int)((long)NE*HD*ID/4/256), 256>>>((const float4*)down, p_downh, (long)NE*HD*ID/4);
    interleave_sgu_kernel<<<(int)((long)2*ISD*HD/4/256), 256>>>(sgp, sup, p_sguh);
    tohalf4<<<(int)((long)HD*ISD/4/256), 256>>>((const float4*)sdp, p_sdph, (long)HD*ISD/4);
    tohalf4<<<(int)((long)N*HD/4/256), 256>>>((const float4*)x, p_xh, (long)N*HD/4);

    // expert gate_up (fused silu): hbuf[slot][512] (fp16) from gathered x
    gemm_f16<<<dim3(MTILES, 4), 256, SMEM_DYN>>>(
        p_xh, p_guph, p_hbuf, HD, ID, p_tok_idx, p_blk_e, (long)2*ID*HD, 1, 1);
    // expert down: dres[slot][1024] (f32)
    gemm_f16<<<dim3(MTILES, 4), 256, SMEM_DYN>>>(
        p_hbuf, p_downh, p_dres, ID, HD, nullptr, p_blk_e, (long)HD*ID, 0, 1);
    // shared gate/up (fused silu): gbuf[token][2048] (fp16)
    gemm_f16<<<dim3(N/128, 16), 256, SMEM_DYN>>>(
        p_xh, p_sguh, p_gbuf, HD, ISD, nullptr, nullptr, 0, 1, 0);
    // shared down + fused final combine -> out (f32)
    gemm_f16<<<dim3(N/128, 4), 256, SMEM_DYN>>>(
        p_gbuf, p_sdph, out, ISD, HD, nullptr, nullptr, 0, 2, 0);
}